// round 7
// baseline (speedup 1.0000x reference)
#include <cuda_runtime.h>
#include <cuda_bf16.h>
#include <math.h>
#include <stdint.h>

// ---------------- problem constants ----------------
#define B_     4
#define SEQ    2048
#define D_     512
#define H_     8
#define DH_    64
#define ID_    512
#define MM     266
#define MMP    272          // padded feature dim (16B-aligned rows)
#define INNER_ 1024
#define KW     31
#define LNUM   6
#define ROWS   (B_*SEQ)     // 8192 token rows
#define RH     (ROWS*H_)    // 65536 (b,n,h) rows
#define NBH    (B_*H_)      // 32

// ---------------- device scratch (no allocations allowed) ----------------
__device__ float g_h   [ROWS*D_];
__device__ float g_q   [ROWS*ID_];
__device__ float g_k   [ROWS*ID_];
__device__ float g_v   [ROWS*ID_];
__device__ float g_qp  [NBH*SEQ*MMP];   // [bh][n][m]
__device__ float g_kp  [NBH*SEQ*MMP];   // [bh][n][m]
__device__ float g_ks  [NBH*MMP];
__device__ float g_part[NBH*8*MMP];
__device__ float g_ctx [NBH*MMP*DH_];   // [bh][m][e]
__device__ float g_att [ROWS*ID_];
__device__ float g_ya  [ROWS*INNER_];   // pw1 'a' half
__device__ float g_glu [ROWS*INNER_];
__device__ float g_dw  [ROWS*INNER_];

// weight fragments: bf16 hi/lo in mma.sync B-fragment layout.
// frag unit (n8-tile, k16-tile) = 128 uint32: [plane(2)][lane(32)][reg(2)]
// layout: [n8][k16][plane][lane][reg]
#define FR_QKV  (64*32*128)     // 512x512
#define FR_PW1  (256*32*128)    // 2048x512
#define FR_PW2  (64*64*128)     // 512x1024
#define FR_PROJ (48*4*128)      // 266(pad384)x64
#define FR_LSTR (4*FR_QKV + FR_PW1 + FR_PW2 + FR_PROJ)
__device__ uint32_t g_wfrag[(size_t)LNUM * FR_LSTR];   // ~63.5MB

// ---------------- helpers ----------------
__device__ __forceinline__ uint32_t pk2(__nv_bfloat16 a, __nv_bfloat16 b) {
    __nv_bfloat162 t = __halves2bfloat162(a, b);
    return *reinterpret_cast<uint32_t*>(&t);
}
__device__ __forceinline__ uint32_t pkf2(float a, float b) {
    __nv_bfloat162 t = __floats2bfloat162_rn(a, b);
    return *reinterpret_cast<uint32_t*>(&t);
}
__device__ __forceinline__ void ldm4(uint32_t* r, uint32_t addr) {
    asm volatile("ldmatrix.sync.aligned.m8n8.x4.shared.b16 {%0,%1,%2,%3}, [%4];\n"
                 : "=r"(r[0]), "=r"(r[1]), "=r"(r[2]), "=r"(r[3]) : "r"(addr));
}
__device__ __forceinline__ void mma_bf16(float* c, const uint32_t* a, const uint32_t* b) {
    asm volatile(
        "mma.sync.aligned.m16n8k16.row.col.f32.bf16.bf16.f32 "
        "{%0,%1,%2,%3}, {%4,%5,%6,%7}, {%8,%9}, {%0,%1,%2,%3};\n"
        : "+f"(c[0]), "+f"(c[1]), "+f"(c[2]), "+f"(c[3])
        : "r"(a[0]), "r"(a[1]), "r"(a[2]), "r"(a[3]), "r"(b[0]), "r"(b[1]));
}

// ---------------- weight -> fragment converter -----------------------------
// B-frag (m16n8k16, row.col): lane l, reg r: n = n8*8 + l/4, k = k16*16 + (l%4)*2 + r*8
__global__ void wfrag(const float* __restrict__ W, uint32_t* __restrict__ out,
                      int Ndim, int Kdim, int NT8)
{
    const int KT16 = Kdim >> 4;
    size_t idx = (size_t)blockIdx.x * 256 + threadIdx.x;
    size_t total = (size_t)NT8 * KT16 * 128;
    if (idx >= total) return;
    int r     = (int)(idx & 1);
    int l     = (int)((idx >> 1) & 31);
    int plane = (int)((idx >> 6) & 1);
    size_t ft = idx >> 7;
    int k16 = (int)(ft % KT16);
    int n8  = (int)(ft / KT16);
    int n = n8 * 8 + (l >> 2);
    int k = k16 * 16 + (l & 3) * 2 + r * 8;
    float v0 = 0.f, v1 = 0.f;
    if (n < Ndim) {
        float2 vv = *(const float2*)&W[(size_t)n * Kdim + k];
        v0 = vv.x; v1 = vv.y;
    }
    __nv_bfloat16 h0 = __float2bfloat16(v0), h1 = __float2bfloat16(v1);
    uint32_t val = (plane == 0)
        ? pk2(h0, h1)
        : pkf2(v0 - __bfloat162float(h0), v1 - __bfloat162float(h1));
    out[idx] = val;
}

// ======================================================================
// bf16x3-split tensor-core GEMM, B from global fragments (no B smem).
// C = alpha*(A @ W^T) [+bias] ; mode 0: +extra(resid), 1: permute out, 2: gate
// A: Mdim x Kdim row-major (Mdim%128==0, Kdim%32==0)
// ======================================================================
#define ASTR 40
#define PLANE_ELEMS (128*ASTR)
#define PLANE_BYTES (PLANE_ELEMS*2)

__global__ __launch_bounds__(256, 2)
void gemm_tn(const float* __restrict__ A, const uint32_t* __restrict__ Bf,
             float* __restrict__ C, const float* __restrict__ bias,
             const float* __restrict__ extra,
             int Mdim, int Ndim, int Kdim, float alpha, int mode)
{
    __shared__ __align__(16) __nv_bfloat16 Asm[2][128][ASTR];

    const int tid  = threadIdx.x;
    const int lane = tid & 31;
    const int warp = tid >> 5;
    const int wm = (warp & 1) * 64;
    const int wn = (warp >> 1) * 32;
    const int bm = blockIdx.y * 128;
    const int bn = blockIdx.x * 128;
    const int KT16 = Kdim >> 4;
    const int n8_0 = (bn + wn) >> 3;

    const int r0 = tid >> 3;
    const int kk = (tid & 7) * 4;

    float acc[4][4][4];
    #pragma unroll
    for (int i = 0; i < 4; i++)
        #pragma unroll
        for (int j = 0; j < 4; j++)
            #pragma unroll
            for (int t = 0; t < 4; t++) acc[i][j][t] = 0.f;

    const int a_m = lane & 15;
    const int a_k = (lane >> 4) << 3;
    const uint32_t sA = (uint32_t)__cvta_generic_to_shared(&Asm[0][0][0]);

    const int KT = Kdim >> 5;
    for (int kt = 0; kt < KT; kt++) {
        // ---- A fill: fp32 -> bf16 hi/lo planes ----
        #pragma unroll
        for (int u = 0; u < 4; u++) {
            const int row = r0 + u * 32;
            float4 v = *(const float4*)&A[(size_t)(bm + row) * Kdim + kt*32 + kk];
            __nv_bfloat16 h0 = __float2bfloat16(v.x), h1 = __float2bfloat16(v.y),
                          h2 = __float2bfloat16(v.z), h3 = __float2bfloat16(v.w);
            uint2 hi, lo;
            hi.x = pk2(h0, h1); hi.y = pk2(h2, h3);
            lo.x = pkf2(v.x - __bfloat162float(h0), v.y - __bfloat162float(h1));
            lo.y = pkf2(v.z - __bfloat162float(h2), v.w - __bfloat162float(h3));
            *(uint2*)&Asm[0][row][kk] = hi;
            *(uint2*)&Asm[1][row][kk] = lo;
        }
        __syncthreads();

        #pragma unroll
        for (int ks = 0; ks < 2; ks++) {
            // ---- B fragments straight from global (L2-resident weights) ----
            uint32_t bh[4][2], bl[4][2];
            const uint32_t* fb = Bf + ((size_t)n8_0 * KT16 + (kt*2 + ks)) * 128 + lane * 2;
            #pragma unroll
            for (int nt = 0; nt < 4; nt++) {
                const uint32_t* fp = fb + (size_t)nt * KT16 * 128;
                uint2 h  = *(const uint2*)fp;
                uint2 lo = *(const uint2*)(fp + 64);
                bh[nt][0] = h.x;  bh[nt][1] = h.y;
                bl[nt][0] = lo.x; bl[nt][1] = lo.y;
            }
            #pragma unroll
            for (int mt = 0; mt < 4; mt++) {
                uint32_t ah[4], al[4];
                uint32_t addr = sA + (uint32_t)(((wm + mt*16 + a_m) * ASTR) + ks*16 + a_k) * 2;
                ldm4(ah, addr);
                ldm4(al, addr + PLANE_BYTES);
                #pragma unroll
                for (int nt = 0; nt < 4; nt++) {
                    mma_bf16(acc[mt][nt], ah, bh[nt]);
                    mma_bf16(acc[mt][nt], ah, bl[nt]);
                    mma_bf16(acc[mt][nt], al, bh[nt]);
                }
            }
        }
        __syncthreads();
    }

    // ---- epilogue ----
    const int gr = lane >> 2;
    const int gc = (lane & 3) * 2;
    #pragma unroll
    for (int mt = 0; mt < 4; mt++) {
        #pragma unroll
        for (int nt = 0; nt < 4; nt++) {
            const float* cp = acc[mt][nt];
            int row = bm + wm + mt*16 + gr;
            int col = bn + wn + nt*8 + gc;
            #pragma unroll
            for (int half = 0; half < 2; half++) {
                int rr = row + half*8;
                #pragma unroll
                for (int j = 0; j < 2; j++) {
                    int cc = col + j;
                    if (cc < Ndim) {
                        float val = cp[half*2 + j] * alpha;
                        if (bias) val += bias[cc];
                        if (mode == 0) {
                            if (extra) val += extra[(size_t)rr * Ndim + cc];
                            C[(size_t)rr * Ndim + cc] = val;
                        } else if (mode == 1) {
                            int hh = rr & 7;
                            int bn2 = rr >> 3;
                            int bb = bn2 >> 11;
                            int nn = bn2 & 2047;
                            C[((size_t)(bb*8 + hh) * SEQ + nn) * MMP + cc] = val;
                        } else { // mode 2: gate -> a * sigmoid(g)
                            float a = extra[(size_t)rr * Ndim + cc];
                            C[(size_t)rr * Ndim + cc] = a / (1.f + expf(-val));
                        }
                    }
                }
            }
        }
    }
}

// ---------------- LayerNorm over D=512, one block per row -----------------
__global__ void ln_kernel(const float* __restrict__ x, const float* __restrict__ g,
                          const float* __restrict__ b, float* __restrict__ out)
{
    const int r = blockIdx.x;
    const int t = threadIdx.x;
    const float4 v = ((const float4*)(x + (size_t)r * D_))[t];
    float s  = v.x + v.y + v.z + v.w;
    float ss = v.x*v.x + v.y*v.y + v.z*v.z + v.w*v.w;
    __shared__ float rs[128], rss[128];
    rs[t] = s; rss[t] = ss;
    __syncthreads();
    for (int o = 64; o > 0; o >>= 1) {
        if (t < o) { rs[t] += rs[t+o]; rss[t] += rss[t+o]; }
        __syncthreads();
    }
    const float mu   = rs[0] * (1.f / D_);
    const float var  = rss[0] * (1.f / D_) - mu * mu;
    const float rstd = rsqrtf(var + 1e-5f);
    const float4 gg = ((const float4*)g)[t];
    const float4 bb = ((const float4*)b)[t];
    float4 o4;
    o4.x = (v.x - mu) * rstd * gg.x + bb.x;
    o4.y = (v.y - mu) * rstd * gg.y + bb.y;
    o4.z = (v.z - mu) * rstd * gg.z + bb.z;
    o4.w = (v.w - mu) * rstd * gg.w + bb.w;
    ((float4*)(out + (size_t)r * D_))[t] = o4;
}

// ---------------- FAVOR postprocess: warp per row, single pass -------------
__global__ __launch_bounds__(256)
void favor_post2(float* __restrict__ fp, const float* __restrict__ data,
                 int isQuery, float ratio)
{
    const int lane = threadIdx.x & 31;
    const int w    = threadIdx.x >> 5;
    const int bh   = blockIdx.y;
    const int n    = blockIdx.x * 8 + w;
    const int b = bh >> 3, h = bh & 7;

    float* prow = fp + ((size_t)bh * SEQ + n) * MMP;
    const float* drow = data + ((size_t)((b * SEQ + n) * H_) + h) * DH_;

    float2 d2 = ((const float2*)drow)[lane];
    float s = d2.x*d2.x + d2.y*d2.y;
    #pragma unroll
    for (int o = 16; o > 0; o >>= 1) s += __shfl_xor_sync(0xffffffffu, s, o);
    const float diag = s * 0.0625f;

    float v[9];
    #pragma unroll
    for (int j = 0; j < 9; j++) {
        int m = j*32 + lane;
        v[j] = (m < MM) ? prow[m] : -1e30f;
    }

    if (isQuery) {
        float mx = v[0];
        #pragma unroll
        for (int j = 1; j < 9; j++) mx = fmaxf(mx, v[j]);
        #pragma unroll
        for (int o = 16; o > 0; o >>= 1) mx = fmaxf(mx, __shfl_xor_sync(0xffffffffu, mx, o));
        #pragma unroll
        for (int j = 0; j < 9; j++) {
            int m = j*32 + lane;
            if (m < MM)       prow[m] = ratio * (expf(v[j] - diag - mx) + 1e-4f);
            else if (m < MMP) prow[m] = 0.f;
        }
    } else {
        #pragma unroll
        for (int j = 0; j < 9; j++) {
            int m = j*32 + lane;
            if (m < MM)       prow[m] = ratio * expf(v[j] - diag + 1e-4f);
            else if (m < MMP) prow[m] = 0.f;
        }
    }
}

// ---------------- ksum two-stage ---------------
__global__ void ksum1(const float* __restrict__ kp, float* __restrict__ part)
{
    const int bh = blockIdx.y;
    const int chunk = blockIdx.x;
    const int m = threadIdx.x;
    if (m >= MMP) return;
    const float* base = kp + ((size_t)bh * SEQ + chunk * 256) * MMP + m;
    float s0 = 0.f, s1 = 0.f, s2 = 0.f, s3 = 0.f;
    for (int n = 0; n < 256; n += 4) {
        s0 += base[(size_t)(n+0) * MMP];
        s1 += base[(size_t)(n+1) * MMP];
        s2 += base[(size_t)(n+2) * MMP];
        s3 += base[(size_t)(n+3) * MMP];
    }
    part[((size_t)bh * 8 + chunk) * MMP + m] = (s0 + s1) + (s2 + s3);
}
__global__ void ksum2(const float* __restrict__ part, float* __restrict__ ks)
{
    const int bh = blockIdx.x;
    const int m = threadIdx.x;
    if (m >= MMP) return;
    float s = 0.f;
    #pragma unroll
    for (int c = 0; c < 8; c++) s += part[((size_t)bh * 8 + c) * MMP + m];
    ks[(size_t)bh * MMP + m] = s;
}

// ---------------- context: ctx[bh] (MMPx64) = kp[bh]^T @ v[bh] --------------
__global__ __launch_bounds__(256)
void ctx_kernel(const float* __restrict__ kp, const float* __restrict__ v,
                float* __restrict__ ctx)
{
    const int bh = blockIdx.y;
    const int b = bh >> 3, h = bh & 7;
    const int m0 = blockIdx.x * 64;
    const float* kpb = kp + (size_t)bh * SEQ * MMP;
    const float* vb  = v + ((size_t)b * SEQ * H_ + h) * DH_;

    __shared__ float As[32][65];
    __shared__ float Bs[32][65];
    const int tx = threadIdx.x & 15, ty = threadIdx.x >> 4;

    float acc[4][4];
    #pragma unroll
    for (int i = 0; i < 4; i++)
        #pragma unroll
        for (int j = 0; j < 4; j++) acc[i][j] = 0.f;

    for (int n0 = 0; n0 < SEQ; n0 += 32) {
        #pragma unroll
        for (int u = 0; u < 8; u++) {
            int f = threadIdx.x + u*256;
            int nn = f >> 6, mm = f & 63;
            int gm = m0 + mm;
            As[nn][mm] = (gm < MMP) ? kpb[(size_t)(n0 + nn) * MMP + gm] : 0.f;
            Bs[nn][mm] = vb[(size_t)(n0 + nn) * (H_*DH_) + mm];
        }
        __syncthreads();
        #pragma unroll
        for (int kk2 = 0; kk2 < 32; kk2++) {
            float a[4], bb[4];
            #pragma unroll
            for (int i = 0; i < 4; i++) a[i] = As[kk2][ty*4 + i];
            #pragma unroll
            for (int j = 0; j < 4; j++) bb[j] = Bs[kk2][tx*4 + j];
            #pragma unroll
            for (int i = 0; i < 4; i++)
                #pragma unroll
                for (int j = 0; j < 4; j++) acc[i][j] += a[i] * bb[j];
        }
        __syncthreads();
    }

    float* cb = ctx + (size_t)bh * MMP * DH_;
    #pragma unroll
    for (int i = 0; i < 4; i++) {
        int m = m0 + ty*4 + i;
        if (m < MMP) {
            #pragma unroll
            for (int j = 0; j < 4; j++)
                cb[(size_t)m * DH_ + tx*4 + j] = acc[i][j];
        }
    }
}

// ---------------- attention out, smem-tiled with ctx reuse ------------------
__global__ __launch_bounds__(256)
void attn_out2(const float* __restrict__ qp, const float* __restrict__ ks,
               const float* __restrict__ ctx, float* __restrict__ out)
{
    const int bh = blockIdx.y;
    const int b = bh >> 3, h = bh & 7;
    const int n0 = blockIdx.x * 32;
    const int t = threadIdx.x;
    const int ri = t >> 3;
    const int e0 = (t & 7) * 8;

    __shared__ __align__(16) float cs[64][68];
    __shared__ __align__(16) float qs[32][68];
    __shared__ float dsum[32];

    if (t < 32) dsum[t] = 0.f;
    float acc[8];
    #pragma unroll
    for (int j = 0; j < 8; j++) acc[j] = 0.f;

    const float* ksb = ks + (size_t)bh * MMP;
    const float* qpb = qp + ((size_t)bh * SEQ + n0) * MMP;
    const float4 z4 = make_float4(0.f, 0.f, 0.f, 0.f);

    for (int m0 = 0; m0 < MMP; m0 += 64) {
        #pragma unroll
        for (int u = 0; u < 4; u++) {
            int f = t + u*256;
            int mm = f >> 4;
            int ee = (f & 15) * 4;
            int gm = m0 + mm;
            float4 v = (gm < MMP) ? *(const float4*)&ctx[((size_t)bh * MMP + gm) * DH_ + ee] : z4;
            *(float4*)&cs[mm][ee] = v;
        }
        #pragma unroll
        for (int u = 0; u < 2; u++) {
            int f = t + u*256;
            int rr = f >> 4;
            int m4 = (f & 15) * 4;
            int gm = m0 + m4;
            float4 v = (gm < MMP) ? *(const float4*)&qpb[(size_t)rr * MMP + gm] : z4;
            *(float4*)&qs[rr][m4] = v;
        }
        __syncthreads();

        if (t < 32) {
            const int lim = (MMP - m0 < 64) ? (MMP - m0) : 64;
            float s = 0.f;
            for (int mm = 0; mm < lim; mm++) s += qs[t][mm] * ksb[m0 + mm];
            dsum[t] += s;
        }

        #pragma unroll 4
        for (int mm = 0; mm < 64; mm++) {
            float qv = qs[ri][mm];
            float4 c0 = *(const float4*)&cs[mm][e0];
            float4 c1 = *(const float4*)&cs[mm][e0 + 4];
            acc[0] += qv * c0.x; acc[1] += qv * c0.y;
            acc[2] += qv * c0.z; acc[3] += qv * c0.w;
            acc[4] += qv * c1.x; acc[5] += qv * c1.y;
            acc[6] += qv * c1.z; acc[7] += qv * c1.w;
        }
        __syncthreads();
    }

    const float dinv = 1.f / (dsum[ri] + 1e-8f);
    float* orow = out + ((size_t)(b * SEQ + n0 + ri) * H_ + h) * DH_ + e0;
    float4 o0 = make_float4(acc[0]*dinv, acc[1]*dinv, acc[2]*dinv, acc[3]*dinv);
    float4 o1 = make_float4(acc[4]*dinv, acc[5]*dinv, acc[6]*dinv, acc[7]*dinv);
    *(float4*)&orow[0] = o0;
    *(float4*)&orow[4] = o1;
}

// ---------------- depthwise conv (K=31, pad 15) + SiLU, tiled ---------------
#define DC_CH 128
#define DC_TN 32
__global__ __launch_bounds__(256)
void dwconv2(const float* __restrict__ gin, const float* __restrict__ w,
             const float* __restrict__ bias, float* __restrict__ out)
{
    __shared__ float sin_[DC_TN + 30][DC_CH];
    __shared__ float sw[DC_CH * KW];

    const int c0 = blockIdx.x * DC_CH;
    const int n0 = blockIdx.y * DC_TN;
    const int b  = blockIdx.z;
    const int t  = threadIdx.x;

    for (int i = t; i < DC_CH * KW; i += 256)
        sw[i] = w[(size_t)c0 * KW + i];
    #pragma unroll
    for (int u = 0; u < (DC_TN + 30) * DC_CH / 256; u++) {
        int f = t + u * 256;
        int rowi = f >> 7;
        int ch = f & 127;
        int n = n0 + rowi - 15;
        sin_[rowi][ch] = ((unsigned)n < SEQ)
            ? gin[((size_t)(b * SEQ + n) << 10) + c0 + ch] : 0.f;
    }
    __syncthreads();

    const int ch = t & 127;
    const int nl0 = (t >> 7) * 16;

    float wr[KW];
    #pragma unroll
    for (int k = 0; k < KW; k++) wr[k] = sw[ch * KW + k];
    const float bb = bias[c0 + ch];

    #pragma unroll
    for (int i = 0; i < 16; i++) {
        float acc = bb;
        #pragma unroll
        for (int k = 0; k < KW; k++)
            acc += sin_[nl0 + i + k][ch] * wr[k];
        float o = acc / (1.f + expf(-acc));
        out[((size_t)(b * SEQ + n0 + nl0 + i) << 10) + c0 + ch] = o;
    }
}

// ---------------- host orchestration ----------------------------------------
static inline void run_gemm(const float* A, const uint32_t* Bf, float* C,
                            const float* bias, const float* extra,
                            int Mdim, int Ndim, int Kdim, float alpha, int mode)
{
    dim3 grid((Ndim + 127) / 128, Mdim / 128);
    gemm_tn<<<grid, 256>>>(A, Bf, C, bias, extra, Mdim, Ndim, Kdim, alpha, mode);
}
static inline void run_wfrag(const float* W, uint32_t* out, int Ndim, int Kdim, int NT8)
{
    size_t total = (size_t)NT8 * (Kdim >> 4) * 128;
    wfrag<<<(unsigned)((total + 255) / 256), 256>>>(W, out, Ndim, Kdim, NT8);
}

extern "C" void kernel_launch(void* const* d_in, const int* in_sizes, int n_in,
                              void* d_out, int out_size)
{
    const float* x    = (const float*)d_in[0];
    const float* ln1g = (const float*)d_in[1];
    const float* ln1b = (const float*)d_in[2];
    const float* wq   = (const float*)d_in[3];
    const float* bq   = (const float*)d_in[4];
    const float* wk   = (const float*)d_in[5];
    const float* bk   = (const float*)d_in[6];
    const float* wv   = (const float*)d_in[7];
    const float* bv   = (const float*)d_in[8];
    const float* wo   = (const float*)d_in[9];
    const float* bo   = (const float*)d_in[10];
    const float* proj = (const float*)d_in[11];
    const float* ln2g = (const float*)d_in[12];
    const float* ln2b = (const float*)d_in[13];
    const float* pw1w = (const float*)d_in[14];
    const float* pw1b = (const float*)d_in[15];
    const float* dww  = (const float*)d_in[16];
    const float* dwb  = (const float*)d_in[17];
    const float* pw2w = (const float*)d_in[18];
    const float* pw2b = (const float*)d_in[19];
    float* xo = (float*)d_out;

    float *h, *q, *k, *v, *qp, *kp, *ks, *part, *ctx, *att, *ya, *glu, *dw;
    uint32_t* wf;
    cudaGetSymbolAddress((void**)&h,    g_h);
    cudaGetSymbolAddress((void**)&q,    g_q);
    cudaGetSymbolAddress((void**)&k,    g_k);
    cudaGetSymbolAddress((void**)&v,    g_v);
    cudaGetSymbolAddress((void**)&qp,   g_qp);
    cudaGetSymbolAddress((void**)&kp,   g_kp);
    cudaGetSymbolAddress((void**)&ks,   g_ks);
    cudaGetSymbolAddress((void**)&part, g_part);
    cudaGetSymbolAddress((void**)&ctx,  g_ctx);
    cudaGetSymbolAddress((void**)&att,  g_att);
    cudaGetSymbolAddress((void**)&ya,   g_ya);
    cudaGetSymbolAddress((void**)&glu,  g_glu);
    cudaGetSymbolAddress((void**)&dw,   g_dw);
    cudaGetSymbolAddress((void**)&wf,   g_wfrag);

    // per-layer fragment offsets
    const size_t OFF_WQ = 0;
    const size_t OFF_WK = OFF_WQ + FR_QKV;
    const size_t OFF_WV = OFF_WK + FR_QKV;
    const size_t OFF_WO = OFF_WV + FR_QKV;
    const size_t OFF_P1 = OFF_WO + FR_QKV;
    const size_t OFF_P2 = OFF_P1 + FR_PW1;
    const size_t OFF_PR = OFF_P2 + FR_PW2;

    // ---- convert all weights to fragment planes (runs once per launch) ----
    for (int l = 0; l < LNUM; l++) {
        uint32_t* lw = wf + (size_t)l * FR_LSTR;
        run_wfrag(wq   + (size_t)l*ID_*D_,    lw + OFF_WQ, 512, 512, 64);
        run_wfrag(wk   + (size_t)l*ID_*D_,    lw + OFF_WK, 512, 512, 64);
        run_wfrag(wv   + (size_t)l*ID_*D_,    lw + OFF_WV, 512, 512, 64);
        run_wfrag(wo   + (size_t)l*ID_*D_,    lw + OFF_WO, 512, 512, 64);
        run_wfrag(pw1w + (size_t)l*2048*D_,   lw + OFF_P1, 2048, 512, 256);
        run_wfrag(pw2w + (size_t)l*D_*INNER_, lw + OFF_P2, 512, 1024, 64);
        run_wfrag(proj + (size_t)l*MM*DH_,    lw + OFF_PR, 266, 64, 48);
    }

    cudaMemcpyAsync(xo, x, (size_t)ROWS * D_ * sizeof(float),
                    cudaMemcpyDeviceToDevice);

    const float dn    = (float)(1.0 / sqrt(sqrt(64.0)));
    const float ratio = (float)(1.0 / sqrt(266.0));

    for (int l = 0; l < LNUM; l++) {
        uint32_t* lw = wf + (size_t)l * FR_LSTR;

        ln_kernel<<<ROWS, 128>>>(xo, ln1g + (size_t)l*D_, ln1b + (size_t)l*D_, h);
        run_gemm(h, lw + OFF_WQ, q, bq + (size_t)l*ID_, nullptr, ROWS, ID_, D_, 1.f, 0);
        run_gemm(h, lw + OFF_WK, k, bk + (size_t)l*ID_, nullptr, ROWS, ID_, D_, 1.f, 0);
        run_gemm(h, lw + OFF_WV, v, bv + (size_t)l*ID_, nullptr, ROWS, ID_, D_, 1.f, 0);
        run_gemm(q, lw + OFF_PR, qp, nullptr, nullptr, RH, MM, DH_, dn, 1);
        run_gemm(k, lw + OFF_PR, kp, nullptr, nullptr, RH, MM, DH_, dn, 1);
        {
            dim3 fg(SEQ / 8, NBH);
            favor_post2<<<fg, 256>>>(qp, q, 1, ratio);
            favor_post2<<<fg, 256>>>(kp, k, 0, ratio);
        }
        {
            dim3 k1(8, NBH);
            ksum1<<<k1, 288>>>(kp, part);
            ksum2<<<NBH, 288>>>(part, ks);
            dim3 cg((MMP + 63) / 64, NBH);
            ctx_kernel<<<cg, 256>>>(kp, v, ctx);
            dim3 ag(SEQ / 32, NBH);
            attn_out2<<<ag, 256>>>(qp, ks, ctx, att);
        }
        run_gemm(att, lw + OFF_WO, xo, bo + (size_t)l*D_, xo, ROWS, D_, ID_, 1.f, 0);
        ln_kernel<<<ROWS, 128>>>(xo, ln2g + (size_t)l*D_, ln2b + (size_t)l*D_, h);
        // pw1 split: a-half, then g-half with fused GLU
        run_gemm(h, lw + OFF_P1, ya, pw1b + (size_t)l*2048, nullptr,
                 ROWS, INNER_, D_, 1.f, 0);
        run_gemm(h, lw + OFF_P1 + (size_t)128*32*128, glu,
                 pw1b + (size_t)l*2048 + INNER_, ya, ROWS, INNER_, D_, 1.f, 2);
        {
            dim3 dg(INNER_/DC_CH, SEQ/DC_TN, B_);
            dwconv2<<<dg, 256>>>(glu, dww + (size_t)l*INNER_*KW, dwb + (size_t)l*INNER_, dw);
        }
        run_gemm(dw, lw + OFF_P2, xo, pw2b + (size_t)l*D_, xo, ROWS, D_, INNER_, 1.f, 0);
    }
}

// round 8
// speedup vs baseline: 1.0333x; 1.0333x over previous
#include <cuda_runtime.h>
#include <cuda_bf16.h>
#include <math.h>
#include <stdint.h>

// ---------------- problem constants ----------------
#define B_     4
#define SEQ    2048
#define D_     512
#define H_     8
#define DH_    64
#define ID_    512
#define MM     266
#define MMP    272          // padded feature dim
#define INNER_ 1024
#define KW     31
#define LNUM   6
#define ROWS   (B_*SEQ)     // 8192 token rows
#define RH     (ROWS*H_)    // 65536 (b,n,h) rows
#define NBH    (B_*H_)      // 32

// ---------------- device scratch ----------------
__device__ float g_h   [ROWS*D_];
__device__ float g_qkv [3*(size_t)ROWS*ID_];   // q | k | v, each [rh][64] flat
__device__ float g_fp  [2*(size_t)RH*MMP];     // qp | kp, each [rh][272] flat
__device__ float g_ks  [NBH*MMP];
__device__ float g_part[NBH*8*MMP];
__device__ float g_ctx [NBH*MMP*DH_];          // [bh][m][e]
__device__ float g_att [ROWS*ID_];
__device__ float g_ya  [ROWS*INNER_];
__device__ float g_glu [ROWS*INNER_];
__device__ float g_dw  [ROWS*INNER_];
__device__ float g_qkvbias[LNUM*1536];

// weight fragments: bf16 hi/lo in mma.sync B-fragment layout.
#define FR_QKV  (64*32*128)     // 512x512
#define FR_PW1  (256*32*128)    // 2048x512
#define FR_PW2  (64*64*128)     // 512x1024
#define FR_PROJ (48*4*128)      // 266(pad384)x64
#define FR_LSTR (4*FR_QKV + FR_PW1 + FR_PW2 + FR_PROJ)
__device__ uint32_t g_wfrag[(size_t)LNUM * FR_LSTR];

// ---------------- helpers ----------------
__device__ __forceinline__ uint32_t pk2(__nv_bfloat16 a, __nv_bfloat16 b) {
    __nv_bfloat162 t = __halves2bfloat162(a, b);
    return *reinterpret_cast<uint32_t*>(&t);
}
__device__ __forceinline__ uint32_t pkf2(float a, float b) {
    __nv_bfloat162 t = __floats2bfloat162_rn(a, b);
    return *reinterpret_cast<uint32_t*>(&t);
}
__device__ __forceinline__ void ldm4(uint32_t* r, uint32_t addr) {
    asm volatile("ldmatrix.sync.aligned.m8n8.x4.shared.b16 {%0,%1,%2,%3}, [%4];\n"
                 : "=r"(r[0]), "=r"(r[1]), "=r"(r[2]), "=r"(r[3]) : "r"(addr));
}
__device__ __forceinline__ void mma_bf16(float* c, const uint32_t* a, const uint32_t* b) {
    asm volatile(
        "mma.sync.aligned.m16n8k16.row.col.f32.bf16.bf16.f32 "
        "{%0,%1,%2,%3}, {%4,%5,%6,%7}, {%8,%9}, {%0,%1,%2,%3};\n"
        : "+f"(c[0]), "+f"(c[1]), "+f"(c[2]), "+f"(c[3])
        : "r"(a[0]), "r"(a[1]), "r"(a[2]), "r"(a[3]), "r"(b[0]), "r"(b[1]));
}

// ---------------- weight -> fragment converter -----------------------------
__global__ void wfrag(const float* __restrict__ W, uint32_t* __restrict__ out,
                      int Ndim, int Kdim, int NT8)
{
    const int KT16 = Kdim >> 4;
    size_t idx = (size_t)blockIdx.x * 256 + threadIdx.x;
    size_t total = (size_t)NT8 * KT16 * 128;
    if (idx >= total) return;
    int r     = (int)(idx & 1);
    int l     = (int)((idx >> 1) & 31);
    int plane = (int)((idx >> 6) & 1);
    size_t ft = idx >> 7;
    int k16 = (int)(ft % KT16);
    int n8  = (int)(ft / KT16);
    int n = n8 * 8 + (l >> 2);
    int k = k16 * 16 + (l & 3) * 2 + r * 8;
    float v0 = 0.f, v1 = 0.f;
    if (n < Ndim) {
        float2 vv = *(const float2*)&W[(size_t)n * Kdim + k];
        v0 = vv.x; v1 = vv.y;
    }
    __nv_bfloat16 h0 = __float2bfloat16(v0), h1 = __float2bfloat16(v1);
    uint32_t val = (plane == 0)
        ? pk2(h0, h1)
        : pkf2(v0 - __bfloat162float(h0), v1 - __bfloat162float(h1));
    out[idx] = val;
}

__global__ void biascat(const float* __restrict__ bq, const float* __restrict__ bk,
                        const float* __restrict__ bv, float* __restrict__ out)
{
    int i = blockIdx.x * 256 + threadIdx.x;   // over LNUM*512
    if (i < LNUM * 512) {
        int l = i >> 9, c = i & 511;
        out[l*1536 + c]        = bq[i];
        out[l*1536 + 512 + c]  = bk[i];
        out[l*1536 + 1024 + c] = bv[i];
    }
}

// ======================================================================
// bf16x3-split tensor-core GEMM, B from global fragments.
// modes: 0 normal (+extra resid), 1 stride-MMP output (favor),
//        2 gate (a*sigmoid), 3 qkv 3-way split output
// ======================================================================
#define ASTR 40
#define PLANE_ELEMS (128*ASTR)
#define PLANE_BYTES (PLANE_ELEMS*2)

__global__ __launch_bounds__(256, 2)
void gemm_tn(const float* __restrict__ A, const uint32_t* __restrict__ Bf,
             float* __restrict__ C, const float* __restrict__ bias,
             const float* __restrict__ extra,
             int Mdim, int Ndim, int Kdim, float alpha, int mode)
{
    __shared__ __align__(16) __nv_bfloat16 Asm[2][128][ASTR];

    const int tid  = threadIdx.x;
    const int lane = tid & 31;
    const int warp = tid >> 5;
    const int wm = (warp & 1) * 64;
    const int wn = (warp >> 1) * 32;
    const int bm = blockIdx.y * 128;
    const int bn = blockIdx.x * 128;
    const int KT16 = Kdim >> 4;
    const int n8_0 = (bn + wn) >> 3;

    const int r0 = tid >> 3;
    const int kk = (tid & 7) * 4;

    float acc[4][4][4];
    #pragma unroll
    for (int i = 0; i < 4; i++)
        #pragma unroll
        for (int j = 0; j < 4; j++)
            #pragma unroll
            for (int t = 0; t < 4; t++) acc[i][j][t] = 0.f;

    const int a_m = lane & 15;
    const int a_k = (lane >> 4) << 3;
    const uint32_t sA = (uint32_t)__cvta_generic_to_shared(&Asm[0][0][0]);

    const int KT = Kdim >> 5;
    for (int kt = 0; kt < KT; kt++) {
        #pragma unroll
        for (int u = 0; u < 4; u++) {
            const int row = r0 + u * 32;
            float4 v = *(const float4*)&A[(size_t)(bm + row) * Kdim + kt*32 + kk];
            __nv_bfloat16 h0 = __float2bfloat16(v.x), h1 = __float2bfloat16(v.y),
                          h2 = __float2bfloat16(v.z), h3 = __float2bfloat16(v.w);
            uint2 hi, lo;
            hi.x = pk2(h0, h1); hi.y = pk2(h2, h3);
            lo.x = pkf2(v.x - __bfloat162float(h0), v.y - __bfloat162float(h1));
            lo.y = pkf2(v.z - __bfloat162float(h2), v.w - __bfloat162float(h3));
            *(uint2*)&Asm[0][row][kk] = hi;
            *(uint2*)&Asm[1][row][kk] = lo;
        }
        __syncthreads();

        #pragma unroll
        for (int ks = 0; ks < 2; ks++) {
            uint32_t bh[4][2], bl[4][2];
            const uint32_t* fb = Bf + ((size_t)n8_0 * KT16 + (kt*2 + ks)) * 128 + lane * 2;
            #pragma unroll
            for (int nt = 0; nt < 4; nt++) {
                const uint32_t* fp = fb + (size_t)nt * KT16 * 128;
                uint2 h  = *(const uint2*)fp;
                uint2 lo = *(const uint2*)(fp + 64);
                bh[nt][0] = h.x;  bh[nt][1] = h.y;
                bl[nt][0] = lo.x; bl[nt][1] = lo.y;
            }
            #pragma unroll
            for (int mt = 0; mt < 4; mt++) {
                uint32_t ah[4], al[4];
                uint32_t addr = sA + (uint32_t)(((wm + mt*16 + a_m) * ASTR) + ks*16 + a_k) * 2;
                ldm4(ah, addr);
                ldm4(al, addr + PLANE_BYTES);
                #pragma unroll
                for (int nt = 0; nt < 4; nt++) {
                    mma_bf16(acc[mt][nt], ah, bh[nt]);
                    mma_bf16(acc[mt][nt], ah, bl[nt]);
                    mma_bf16(acc[mt][nt], al, bh[nt]);
                }
            }
        }
        __syncthreads();
    }

    // ---- epilogue ----
    const int gr = lane >> 2;
    const int gc = (lane & 3) * 2;
    #pragma unroll
    for (int mt = 0; mt < 4; mt++) {
        #pragma unroll
        for (int nt = 0; nt < 4; nt++) {
            const float* cp = acc[mt][nt];
            int row = bm + wm + mt*16 + gr;
            int col = bn + wn + nt*8 + gc;
            #pragma unroll
            for (int half = 0; half < 2; half++) {
                int rr = row + half*8;
                #pragma unroll
                for (int j = 0; j < 2; j++) {
                    int cc = col + j;
                    if (cc < Ndim) {
                        float val = cp[half*2 + j] * alpha;
                        if (bias) val += bias[cc];
                        if (mode == 0) {
                            if (extra) val += extra[(size_t)rr * Ndim + cc];
                            C[(size_t)rr * Ndim + cc] = val;
                        } else if (mode == 1) {
                            // flat [rh][MMP] output (coalesced)
                            C[(size_t)rr * MMP + cc] = val;
                        } else if (mode == 2) {
                            float a = extra[(size_t)rr * Ndim + cc];
                            C[(size_t)rr * Ndim + cc] = a / (1.f + expf(-val));
                        } else { // mode 3: q|k|v split
                            C[(size_t)(cc >> 9) * ((size_t)ROWS * ID_)
                              + (size_t)rr * ID_ + (cc & 511)] = val;
                        }
                    }
                }
            }
        }
    }
}

// ---------------- LayerNorm over D=512 -----------------
__global__ void ln_kernel(const float* __restrict__ x, const float* __restrict__ g,
                          const float* __restrict__ b, float* __restrict__ out)
{
    const int r = blockIdx.x;
    const int t = threadIdx.x;
    const float4 v = ((const float4*)(x + (size_t)r * D_))[t];
    float s  = v.x + v.y + v.z + v.w;
    float ss = v.x*v.x + v.y*v.y + v.z*v.z + v.w*v.w;
    __shared__ float rs[128], rss[128];
    rs[t] = s; rss[t] = ss;
    __syncthreads();
    for (int o = 64; o > 0; o >>= 1) {
        if (t < o) { rs[t] += rs[t+o]; rss[t] += rss[t+o]; }
        __syncthreads();
    }
    const float mu   = rs[0] * (1.f / D_);
    const float var  = rss[0] * (1.f / D_) - mu * mu;
    const float rstd = rsqrtf(var + 1e-5f);
    const float4 gg = ((const float4*)g)[t];
    const float4 bb = ((const float4*)b)[t];
    float4 o4;
    o4.x = (v.x - mu) * rstd * gg.x + bb.x;
    o4.y = (v.y - mu) * rstd * gg.y + bb.y;
    o4.z = (v.z - mu) * rstd * gg.z + bb.z;
    o4.w = (v.w - mu) * rstd * gg.w + bb.w;
    ((float4*)(out + (size_t)r * D_))[t] = o4;
}

// ---------------- FAVOR postprocess: warp per row, q and k in one launch ----
// fp: combined qp|kp base. data: combined q|k flat base (q,k adjacent).
__global__ __launch_bounds__(256)
void favor_post3(float* __restrict__ fp, const float* __restrict__ data, float ratio)
{
    const int lane = threadIdx.x & 31;
    const int w    = threadIdx.x >> 5;
    const size_t rh = (size_t)blockIdx.x * 8 + w;   // 0..2RH-1
    const int isQ = rh < (size_t)RH;

    float* prow = fp + rh * MMP;
    const float* drow = data + rh * DH_;

    float2 d2 = ((const float2*)drow)[lane];
    float s = d2.x*d2.x + d2.y*d2.y;
    #pragma unroll
    for (int o = 16; o > 0; o >>= 1) s += __shfl_xor_sync(0xffffffffu, s, o);
    const float diag = s * 0.0625f;

    float v[9];
    #pragma unroll
    for (int j = 0; j < 9; j++) {
        int m = j*32 + lane;
        v[j] = (m < MM) ? prow[m] : -1e30f;
    }

    if (isQ) {
        float mx = v[0];
        #pragma unroll
        for (int j = 1; j < 9; j++) mx = fmaxf(mx, v[j]);
        #pragma unroll
        for (int o = 16; o > 0; o >>= 1) mx = fmaxf(mx, __shfl_xor_sync(0xffffffffu, mx, o));
        #pragma unroll
        for (int j = 0; j < 9; j++) {
            int m = j*32 + lane;
            if (m < MM)       prow[m] = ratio * (expf(v[j] - diag - mx) + 1e-4f);
            else if (m < MMP) prow[m] = 0.f;
        }
    } else {
        #pragma unroll
        for (int j = 0; j < 9; j++) {
            int m = j*32 + lane;
            if (m < MM)       prow[m] = ratio * expf(v[j] - diag + 1e-4f);
            else if (m < MMP) prow[m] = 0.f;
        }
    }
}

// ---------------- ksum two-stage (kp flat [rh][MMP]) ---------------
__global__ void ksum1(const float* __restrict__ kp, float* __restrict__ part)
{
    const int bh = blockIdx.y;
    const int chunk = blockIdx.x;
    const int m = threadIdx.x;
    if (m >= MMP) return;
    const int b = bh >> 3, h = bh & 7;
    const float* base = kp + ((size_t)(b * SEQ + chunk * 256) * H_ + h) * MMP + m;
    const size_t stride = (size_t)H_ * MMP;
    float s0 = 0.f, s1 = 0.f, s2 = 0.f, s3 = 0.f;
    for (int n = 0; n < 256; n += 4) {
        s0 += base[(n+0) * stride];
        s1 += base[(n+1) * stride];
        s2 += base[(n+2) * stride];
        s3 += base[(n+3) * stride];
    }
    part[((size_t)bh * 8 + chunk) * MMP + m] = (s0 + s1) + (s2 + s3);
}
__global__ void ksum2(const float* __restrict__ part, float* __restrict__ ks)
{
    const int bh = blockIdx.x;
    const int m = threadIdx.x;
    if (m >= MMP) return;
    float s = 0.f;
    #pragma unroll
    for (int c = 0; c < 8; c++) s += part[((size_t)bh * 8 + c) * MMP + m];
    ks[(size_t)bh * MMP + m] = s;
}

// ---------------- context: ctx[bh] (MMPx64) = kp[bh]^T @ v[bh] --------------
__global__ __launch_bounds__(256)
void ctx_kernel(const float* __restrict__ kp, const float* __restrict__ v,
                float* __restrict__ ctx)
{
    const int bh = blockIdx.y;
    const int b = bh >> 3, h = bh & 7;
    const int m0 = blockIdx.x * 64;
    const float* kpb = kp + ((size_t)(b * SEQ) * H_ + h) * MMP;
    const float* vb  = v + ((size_t)b * SEQ * H_ + h) * DH_;
    const size_t kstride = (size_t)H_ * MMP;

    __shared__ float As[32][65];
    __shared__ float Bs[32][65];
    const int tx = threadIdx.x & 15, ty = threadIdx.x >> 4;

    float acc[4][4];
    #pragma unroll
    for (int i = 0; i < 4; i++)
        #pragma unroll
        for (int j = 0; j < 4; j++) acc[i][j] = 0.f;

    for (int n0 = 0; n0 < SEQ; n0 += 32) {
        #pragma unroll
        for (int u = 0; u < 8; u++) {
            int f = threadIdx.x + u*256;
            int nn = f >> 6, mm = f & 63;
            int gm = m0 + mm;
            As[nn][mm] = (gm < MMP) ? kpb[(size_t)(n0 + nn) * kstride + gm] : 0.f;
            Bs[nn][mm] = vb[(size_t)(n0 + nn) * (H_*DH_) + mm];
        }
        __syncthreads();
        #pragma unroll
        for (int kk2 = 0; kk2 < 32; kk2++) {
            float a[4], bb[4];
            #pragma unroll
            for (int i = 0; i < 4; i++) a[i] = As[kk2][ty*4 + i];
            #pragma unroll
            for (int j = 0; j < 4; j++) bb[j] = Bs[kk2][tx*4 + j];
            #pragma unroll
            for (int i = 0; i < 4; i++)
                #pragma unroll
                for (int j = 0; j < 4; j++) acc[i][j] += a[i] * bb[j];
        }
        __syncthreads();
    }

    float* cb = ctx + (size_t)bh * MMP * DH_;
    #pragma unroll
    for (int i = 0; i < 4; i++) {
        int m = m0 + ty*4 + i;
        if (m < MMP) {
            #pragma unroll
            for (int j = 0; j < 4; j++)
                cb[(size_t)m * DH_ + tx*4 + j] = acc[i][j];
        }
    }
}

// ---------------- attention out (qp flat layout) ------------------
__global__ __launch_bounds__(256)
void attn_out2(const float* __restrict__ qp, const float* __restrict__ ks,
               const float* __restrict__ ctx, float* __restrict__ out)
{
    const int bh = blockIdx.y;
    const int b = bh >> 3, h = bh & 7;
    const int n0 = blockIdx.x * 32;
    const int t = threadIdx.x;
    const int ri = t >> 3;
    const int e0 = (t & 7) * 8;

    __shared__ __align__(16) float cs[64][68];
    __shared__ __align__(16) float qs[32][68];
    __shared__ float dsum[32];

    if (t < 32) dsum[t] = 0.f;
    float acc[8];
    #pragma unroll
    for (int j = 0; j < 8; j++) acc[j] = 0.f;

    const float* ksb = ks + (size_t)bh * MMP;
    const float* qpb = qp + ((size_t)(b * SEQ + n0) * H_ + h) * MMP;
    const size_t qstride = (size_t)H_ * MMP;
    const float4 z4 = make_float4(0.f, 0.f, 0.f, 0.f);

    for (int m0 = 0; m0 < MMP; m0 += 64) {
        #pragma unroll
        for (int u = 0; u < 4; u++) {
            int f = t + u*256;
            int mm = f >> 4;
            int ee = (f & 15) * 4;
            int gm = m0 + mm;
            float4 v = (gm < MMP) ? *(const float4*)&ctx[((size_t)bh * MMP + gm) * DH_ + ee] : z4;
            *(float4*)&cs[mm][ee] = v;
        }
        #pragma unroll
        for (int u = 0; u < 2; u++) {
            int f = t + u*256;
            int rr = f >> 4;
            int m4 = (f & 15) * 4;
            int gm = m0 + m4;
            float4 v = (gm < MMP) ? *(const float4*)&qpb[(size_t)rr * qstride + gm] : z4;
            *(float4*)&qs[rr][m4] = v;
        }
        __syncthreads();

        if (t < 32) {
            const int lim = (MMP - m0 < 64) ? (MMP - m0) : 64;
            float s = 0.f;
            for (int mm = 0; mm < lim; mm++) s += qs[t][mm] * ksb[m0 + mm];
            dsum[t] += s;
        }

        #pragma unroll 4
        for (int mm = 0; mm < 64; mm++) {
            float qv = qs[ri][mm];
            float4 c0 = *(const float4*)&cs[mm][e0];
            float4 c1 = *(const float4*)&cs[mm][e0 + 4];
            acc[0] += qv * c0.x; acc[1] += qv * c0.y;
            acc[2] += qv * c0.z; acc[3] += qv * c0.w;
            acc[4] += qv * c1.x; acc[5] += qv * c1.y;
            acc[6] += qv * c1.z; acc[7] += qv * c1.w;
        }
        __syncthreads();
    }

    const float dinv = 1.f / (dsum[ri] + 1e-8f);
    float* orow = out + ((size_t)(b * SEQ + n0 + ri) * H_ + h) * DH_ + e0;
    float4 o0 = make_float4(acc[0]*dinv, acc[1]*dinv, acc[2]*dinv, acc[3]*dinv);
    float4 o1 = make_float4(acc[4]*dinv, acc[5]*dinv, acc[6]*dinv, acc[7]*dinv);
    *(float4*)&orow[0] = o0;
    *(float4*)&orow[4] = o1;
}

// ---------------- depthwise conv (K=31, pad 15) + SiLU ---------------
#define DC_CH 128
#define DC_TN 32
__global__ __launch_bounds__(256)
void dwconv2(const float* __restrict__ gin, const float* __restrict__ w,
             const float* __restrict__ bias, float* __restrict__ out)
{
    __shared__ float sin_[DC_TN + 30][DC_CH];
    __shared__ float sw[DC_CH * KW];

    const int c0 = blockIdx.x * DC_CH;
    const int n0 = blockIdx.y * DC_TN;
    const int b  = blockIdx.z;
    const int t  = threadIdx.x;

    for (int i = t; i < DC_CH * KW; i += 256)
        sw[i] = w[(size_t)c0 * KW + i];
    #pragma unroll
    for (int u = 0; u < (DC_TN + 30) * DC_CH / 256; u++) {
        int f = t + u * 256;
        int rowi = f >> 7;
        int ch = f & 127;
        int n = n0 + rowi - 15;
        sin_[rowi][ch] = ((unsigned)n < SEQ)
            ? gin[((size_t)(b * SEQ + n) << 10) + c0 + ch] : 0.f;
    }
    __syncthreads();

    const int ch = t & 127;
    const int nl0 = (t >> 7) * 16;

    float wr[KW];
    #pragma unroll
    for (int k = 0; k < KW; k++) wr[k] = sw[ch * KW + k];
    const float bb = bias[c0 + ch];

    #pragma unroll
    for (int i = 0; i < 16; i++) {
        float acc = bb;
        #pragma unroll
        for (int k = 0; k < KW; k++)
            acc += sin_[nl0 + i + k][ch] * wr[k];
        float o = acc / (1.f + expf(-acc));
        out[((size_t)(b * SEQ + n0 + nl0 + i) << 10) + c0 + ch] = o;
    }
}

// ---------------- host orchestration ----------------------------------------
static inline void run_gemm(const float* A, const uint32_t* Bf, float* C,
                            const float* bias, const float* extra,
                            int Mdim, int Ndim, int Kdim, float alpha, int mode)
{
    dim3 grid((Ndim + 127) / 128, Mdim / 128);
    gemm_tn<<<grid, 256>>>(A, Bf, C, bias, extra, Mdim, Ndim, Kdim, alpha, mode);
}
static inline void run_wfrag(const float* W, uint32_t* out, int Ndim, int Kdim, int NT8)
{
    size_t total = (size_t)NT8 * (Kdim >> 4) * 128;
    wfrag<<<(unsigned)((total + 255) / 256), 256>>>(W, out, Ndim, Kdim, NT8);
}

extern "C" void kernel_launch(void* const* d_in, const int* in_sizes, int n_in,
                              void* d_out, int out_size)
{
    const float* x    = (const float*)d_in[0];
    const float* ln1g = (const float*)d_in[1];
    const float* ln1b = (const float*)d_in[2];
    const float* wq   = (const float*)d_in[3];
    const float* bq   = (const float*)d_in[4];
    const float* wk   = (const float*)d_in[5];
    const float* bk   = (const float*)d_in[6];
    const float* wv   = (const float*)d_in[7];
    const float* bv   = (const float*)d_in[8];
    const float* wo   = (const float*)d_in[9];
    const float* bo   = (const float*)d_in[10];
    const float* proj = (const float*)d_in[11];
    const float* ln2g = (const float*)d_in[12];
    const float* ln2b = (const float*)d_in[13];
    const float* pw1w = (const float*)d_in[14];
    const float* pw1b = (const float*)d_in[15];
    const float* dww  = (const float*)d_in[16];
    const float* dwb  = (const float*)d_in[17];
    const float* pw2w = (const float*)d_in[18];
    const float* pw2b = (const float*)d_in[19];
    float* xo = (float*)d_out;

    float *h, *qkv, *fp, *ks, *part, *ctx, *att, *ya, *glu, *dw, *qkvb;
    uint32_t* wf;
    cudaGetSymbolAddress((void**)&h,    g_h);
    cudaGetSymbolAddress((void**)&qkv,  g_qkv);
    cudaGetSymbolAddress((void**)&fp,   g_fp);
    cudaGetSymbolAddress((void**)&ks,   g_ks);
    cudaGetSymbolAddress((void**)&part, g_part);
    cudaGetSymbolAddress((void**)&ctx,  g_ctx);
    cudaGetSymbolAddress((void**)&att,  g_att);
    cudaGetSymbolAddress((void**)&ya,   g_ya);
    cudaGetSymbolAddress((void**)&glu,  g_glu);
    cudaGetSymbolAddress((void**)&dw,   g_dw);
    cudaGetSymbolAddress((void**)&qkvb, g_qkvbias);
    cudaGetSymbolAddress((void**)&wf,   g_wfrag);

    float* v_buf = qkv + 2 * (size_t)ROWS * ID_;
    float* qp    = fp;
    float* kp    = fp + (size_t)RH * MMP;

    const size_t OFF_WQ = 0;                       // wq|wk|wv contiguous (fused QKV)
    const size_t OFF_WO = OFF_WQ + 3*FR_QKV;
    const size_t OFF_P1 = OFF_WO + FR_QKV;
    const size_t OFF_P2 = OFF_P1 + FR_PW1;
    const size_t OFF_PR = OFF_P2 + FR_PW2;

    // ---- one-time prep (part of the graph; cheap) ----
    for (int l = 0; l < LNUM; l++) {
        uint32_t* lw = wf + (size_t)l * FR_LSTR;
        run_wfrag(wq   + (size_t)l*ID_*D_,    lw + OFF_WQ,            512, 512, 64);
        run_wfrag(wk   + (size_t)l*ID_*D_,    lw + OFF_WQ + FR_QKV,   512, 512, 64);
        run_wfrag(wv   + (size_t)l*ID_*D_,    lw + OFF_WQ + 2*FR_QKV, 512, 512, 64);
        run_wfrag(wo   + (size_t)l*ID_*D_,    lw + OFF_WO, 512, 512, 64);
        run_wfrag(pw1w + (size_t)l*2048*D_,   lw + OFF_P1, 2048, 512, 256);
        run_wfrag(pw2w + (size_t)l*D_*INNER_, lw + OFF_P2, 512, 1024, 64);
        run_wfrag(proj + (size_t)l*MM*DH_,    lw + OFF_PR, 266, 64, 48);
    }
    biascat<<<(LNUM*512 + 255)/256, 256>>>(bq, bk, bv, qkvb);

    cudaMemcpyAsync(xo, x, (size_t)ROWS * D_ * sizeof(float),
                    cudaMemcpyDeviceToDevice);

    const float dn    = (float)(1.0 / sqrt(sqrt(64.0)));
    const float ratio = (float)(1.0 / sqrt(266.0));

    for (int l = 0; l < LNUM; l++) {
        uint32_t* lw = wf + (size_t)l * FR_LSTR;

        ln_kernel<<<ROWS, 128>>>(xo, ln1g + (size_t)l*D_, ln1b + (size_t)l*D_, h);
        // fused QKV: one GEMM, Ndim=1536, 3-way split output
        run_gemm(h, lw + OFF_WQ, qkv, qkvb + (size_t)l*1536, nullptr,
                 ROWS, 1536, D_, 1.f, 3);
        // fused qp|kp feature GEMM: A = q|k flat (2*RH x 64), out flat [rh][MMP]
        run_gemm(qkv, lw + OFF_PR, qp, nullptr, nullptr, 2*RH, MM, DH_, dn, 1);
        favor_post3<<<2*RH/8, 256>>>(fp, qkv, ratio);
        {
            dim3 k1(8, NBH);
            ksum1<<<k1, 288>>>(kp, part);
            ksum2<<<NBH, 288>>>(part, ks);
            dim3 cg((MMP + 63) / 64, NBH);
            ctx_kernel<<<cg, 256>>>(kp, v_buf, ctx);
            dim3 ag(SEQ / 32, NBH);
            attn_out2<<<ag, 256>>>(qp, ks, ctx, att);
        }
        run_gemm(att, lw + OFF_WO, xo, bo + (size_t)l*D_, xo, ROWS, D_, ID_, 1.f, 0);
        ln_kernel<<<ROWS, 128>>>(xo, ln2g + (size_t)l*D_, ln2b + (size_t)l*D_, h);
        run_gemm(h, lw + OFF_P1, ya, pw1b + (size_t)l*2048, nullptr,
                 ROWS, INNER_, D_, 1.f, 0);
        run_gemm(h, lw + OFF_P1 + (size_t)128*32*128, glu,
                 pw1b + (size_t)l*2048 + INNER_, ya, ROWS, INNER_, D_, 1.f, 2);
        {
            dim3 dg(INNER_/DC_CH, SEQ/DC_TN, B_);
            dwconv2<<<dg, 256>>>(glu, dww + (size_t)l*INNER_*KW, dwb + (size_t)l*INNER_, dw);
        }
        run_gemm(dw, lw + OFF_P2, xo, pw2b + (size_t)l*D_, xo, ROWS, D_, INNER_, 1.f, 0);
    }
}

// round 9
// speedup vs baseline: 1.4785x; 1.4309x over previous
#include <cuda_runtime.h>
#include <cuda_bf16.h>
#include <math.h>
#include <stdint.h>

// ---------------- problem constants ----------------
#define B_     4
#define SEQ    2048
#define D_     512
#define H_     8
#define DH_    64
#define ID_    512
#define MM     266
#define MMP    272
#define INNER_ 1024
#define KW     31
#define LNUM   6
#define ROWS   (B_*SEQ)
#define RH     (ROWS*H_)
#define NBH    (B_*H_)

// ---------------- device scratch ----------------
__device__ float g_h    [ROWS*D_];
__device__ float g_qkv  [3*(size_t)ROWS*ID_];   // q | k | v flat [rh][64]
__device__ float g_fp   [2*(size_t)RH*MMP];     // qp | kp flat [rh][272]
__device__ float g_ks   [NBH*MMP];
__device__ float g_part [NBH*8*MMP];
__device__ float g_cpart[(size_t)NBH*8*MMP*DH_]; // ctx partials [bh][kc][272][64]
__device__ float g_ctxT [(size_t)NBH*80*288];    // [bh][e][m]
__device__ float g_att  [ROWS*ID_];
__device__ float g_ya   [ROWS*INNER_];
__device__ float g_glu  [ROWS*INNER_];
__device__ float g_dw   [ROWS*INNER_];
__device__ float g_qkvbias[LNUM*1536];

#define FR_QKV  (64*32*128)
#define FR_PW1  (256*32*128)
#define FR_PW2  (64*64*128)
#define FR_PROJ (48*4*128)
#define FR_LSTR (4*FR_QKV + FR_PW1 + FR_PW2 + FR_PROJ)
__device__ uint32_t g_wfrag[(size_t)LNUM * FR_LSTR];

// ---------------- helpers ----------------
__device__ __forceinline__ uint32_t pk2(__nv_bfloat16 a, __nv_bfloat16 b) {
    __nv_bfloat162 t = __halves2bfloat162(a, b);
    return *reinterpret_cast<uint32_t*>(&t);
}
__device__ __forceinline__ uint32_t pkf2(float a, float b) {
    __nv_bfloat162 t = __floats2bfloat162_rn(a, b);
    return *reinterpret_cast<uint32_t*>(&t);
}
__device__ __forceinline__ void ldm4(uint32_t* r, uint32_t addr) {
    asm volatile("ldmatrix.sync.aligned.m8n8.x4.shared.b16 {%0,%1,%2,%3}, [%4];\n"
                 : "=r"(r[0]), "=r"(r[1]), "=r"(r[2]), "=r"(r[3]) : "r"(addr));
}
__device__ __forceinline__ void ldm4t(uint32_t* r, uint32_t addr) {
    asm volatile("ldmatrix.sync.aligned.m8n8.x4.trans.shared.b16 {%0,%1,%2,%3}, [%4];\n"
                 : "=r"(r[0]), "=r"(r[1]), "=r"(r[2]), "=r"(r[3]) : "r"(addr));
}
__device__ __forceinline__ void mma_bf16(float* c, const uint32_t* a, const uint32_t* b) {
    asm volatile(
        "mma.sync.aligned.m16n8k16.row.col.f32.bf16.bf16.f32 "
        "{%0,%1,%2,%3}, {%4,%5,%6,%7}, {%8,%9}, {%0,%1,%2,%3};\n"
        : "+f"(c[0]), "+f"(c[1]), "+f"(c[2]), "+f"(c[3])
        : "r"(a[0]), "r"(a[1]), "r"(a[2]), "r"(a[3]), "r"(b[0]), "r"(b[1]));
}
// fp32x2 -> bf16 hi/lo planes
__device__ __forceinline__ void splitf4(float4 v, uint2& hi, uint2& lo) {
    __nv_bfloat16 h0 = __float2bfloat16(v.x), h1 = __float2bfloat16(v.y),
                  h2 = __float2bfloat16(v.z), h3 = __float2bfloat16(v.w);
    hi.x = pk2(h0, h1); hi.y = pk2(h2, h3);
    lo.x = pkf2(v.x - __bfloat162float(h0), v.y - __bfloat162float(h1));
    lo.y = pkf2(v.z - __bfloat162float(h2), v.w - __bfloat162float(h3));
}

// ---------------- weight -> fragment converter -----------------------------
__global__ void wfrag(const float* __restrict__ W, uint32_t* __restrict__ out,
                      int Ndim, int Kdim, int NT8)
{
    const int KT16 = Kdim >> 4;
    size_t idx = (size_t)blockIdx.x * 256 + threadIdx.x;
    size_t total = (size_t)NT8 * KT16 * 128;
    if (idx >= total) return;
    int r     = (int)(idx & 1);
    int l     = (int)((idx >> 1) & 31);
    int plane = (int)((idx >> 6) & 1);
    size_t ft = idx >> 7;
    int k16 = (int)(ft % KT16);
    int n8  = (int)(ft / KT16);
    int n = n8 * 8 + (l >> 2);
    int k = k16 * 16 + (l & 3) * 2 + r * 8;
    float v0 = 0.f, v1 = 0.f;
    if (n < Ndim) {
        float2 vv = *(const float2*)&W[(size_t)n * Kdim + k];
        v0 = vv.x; v1 = vv.y;
    }
    __nv_bfloat16 h0 = __float2bfloat16(v0), h1 = __float2bfloat16(v1);
    uint32_t val = (plane == 0)
        ? pk2(h0, h1)
        : pkf2(v0 - __bfloat162float(h0), v1 - __bfloat162float(h1));
    out[idx] = val;
}

__global__ void biascat(const float* __restrict__ bq, const float* __restrict__ bk,
                        const float* __restrict__ bv, float* __restrict__ out)
{
    int i = blockIdx.x * 256 + threadIdx.x;
    if (i < LNUM * 512) {
        int l = i >> 9, c = i & 511;
        out[l*1536 + c]        = bq[i];
        out[l*1536 + 512 + c]  = bk[i];
        out[l*1536 + 1024 + c] = bv[i];
    }
}

// ======================================================================
// main GEMM (weights as fragments). modes: 0 normal(+resid), 1 [rh][MMP] out,
// 2 gate, 3 qkv split
// ======================================================================
#define ASTR 40
#define PLANE_ELEMS (128*ASTR)
#define PLANE_BYTES (PLANE_ELEMS*2)

__global__ __launch_bounds__(256, 2)
void gemm_tn(const float* __restrict__ A, const uint32_t* __restrict__ Bf,
             float* __restrict__ C, const float* __restrict__ bias,
             const float* __restrict__ extra,
             int Mdim, int Ndim, int Kdim, float alpha, int mode)
{
    __shared__ __align__(16) __nv_bfloat16 Asm[2][128][ASTR];

    const int tid  = threadIdx.x;
    const int lane = tid & 31;
    const int warp = tid >> 5;
    const int wm = (warp & 1) * 64;
    const int wn = (warp >> 1) * 32;
    const int bm = blockIdx.y * 128;
    const int bn = blockIdx.x * 128;
    const int KT16 = Kdim >> 4;
    const int n8_0 = (bn + wn) >> 3;

    const int r0 = tid >> 3;
    const int kk = (tid & 7) * 4;

    float acc[4][4][4];
    #pragma unroll
    for (int i = 0; i < 4; i++)
        #pragma unroll
        for (int j = 0; j < 4; j++)
            #pragma unroll
            for (int t = 0; t < 4; t++) acc[i][j][t] = 0.f;

    const int a_m = lane & 15;
    const int a_k = (lane >> 4) << 3;
    const uint32_t sA = (uint32_t)__cvta_generic_to_shared(&Asm[0][0][0]);

    const int KT = Kdim >> 5;
    for (int kt = 0; kt < KT; kt++) {
        #pragma unroll
        for (int u = 0; u < 4; u++) {
            const int row = r0 + u * 32;
            float4 v = *(const float4*)&A[(size_t)(bm + row) * Kdim + kt*32 + kk];
            uint2 hi, lo;
            splitf4(v, hi, lo);
            *(uint2*)&Asm[0][row][kk] = hi;
            *(uint2*)&Asm[1][row][kk] = lo;
        }
        __syncthreads();

        #pragma unroll
        for (int ks = 0; ks < 2; ks++) {
            uint32_t bhf[4][2], blf[4][2];
            const uint32_t* fb = Bf + ((size_t)n8_0 * KT16 + (kt*2 + ks)) * 128 + lane * 2;
            #pragma unroll
            for (int nt = 0; nt < 4; nt++) {
                const uint32_t* fp2 = fb + (size_t)nt * KT16 * 128;
                uint2 h  = *(const uint2*)fp2;
                uint2 lo = *(const uint2*)(fp2 + 64);
                bhf[nt][0] = h.x;  bhf[nt][1] = h.y;
                blf[nt][0] = lo.x; blf[nt][1] = lo.y;
            }
            #pragma unroll
            for (int mt = 0; mt < 4; mt++) {
                uint32_t ah[4], al[4];
                uint32_t addr = sA + (uint32_t)(((wm + mt*16 + a_m) * ASTR) + ks*16 + a_k) * 2;
                ldm4(ah, addr);
                ldm4(al, addr + PLANE_BYTES);
                #pragma unroll
                for (int nt = 0; nt < 4; nt++) {
                    mma_bf16(acc[mt][nt], ah, bhf[nt]);
                    mma_bf16(acc[mt][nt], ah, blf[nt]);
                    mma_bf16(acc[mt][nt], al, bhf[nt]);
                }
            }
        }
        __syncthreads();
    }

    const int gr = lane >> 2;
    const int gc = (lane & 3) * 2;
    #pragma unroll
    for (int mt = 0; mt < 4; mt++) {
        #pragma unroll
        for (int nt = 0; nt < 4; nt++) {
            const float* cp = acc[mt][nt];
            int row = bm + wm + mt*16 + gr;
            int col = bn + wn + nt*8 + gc;
            #pragma unroll
            for (int half = 0; half < 2; half++) {
                int rr = row + half*8;
                #pragma unroll
                for (int j = 0; j < 2; j++) {
                    int cc = col + j;
                    if (cc < Ndim) {
                        float val = cp[half*2 + j] * alpha;
                        if (bias) val += bias[cc];
                        if (mode == 0) {
                            if (extra) val += extra[(size_t)rr * Ndim + cc];
                            C[(size_t)rr * Ndim + cc] = val;
                        } else if (mode == 1) {
                            C[(size_t)rr * MMP + cc] = val;
                        } else if (mode == 2) {
                            float a = extra[(size_t)rr * Ndim + cc];
                            C[(size_t)rr * Ndim + cc] = a / (1.f + expf(-val));
                        } else {
                            C[(size_t)(cc >> 9) * ((size_t)ROWS * ID_)
                              + (size_t)rr * ID_ + (cc & 511)] = val;
                        }
                    }
                }
            }
        }
    }
}

// ======================================================================
// ctx_mma: partial ctx[bh] = kp[bh]^T @ v[bh] over a 256-seq chunk.
// A = kp^T (M=272, K=n), B = v^T (N=64, K=n): both via ldmatrix.trans.
// ======================================================================
#define KPITCH 280
#define VPITCH 72
__global__ __launch_bounds__(256, 1)
void ctx_mma(const float* __restrict__ kp, const float* __restrict__ v,
             float* __restrict__ part)
{
    __shared__ __align__(16) __nv_bfloat16 Kp[2][32][KPITCH];
    __shared__ __align__(16) __nv_bfloat16 Vs[2][32][VPITCH];

    const int tid = threadIdx.x;
    const int lane = tid & 31;
    const int warp = tid >> 5;
    const int kc = blockIdx.x;      // 0..7
    const int bh = blockIdx.y;
    const int b = bh >> 3, h = bh & 7;

    const int nmt = (warp == 0) ? 3 : 2;
    int mts[3];
    mts[0] = 2*warp; mts[1] = 2*warp + 1; mts[2] = 16;

    float acc[3][8][4];
    #pragma unroll
    for (int t = 0; t < 3; t++)
        #pragma unroll
        for (int n = 0; n < 8; n++)
            #pragma unroll
            for (int j = 0; j < 4; j++) acc[t][n][j] = 0.f;

    const float* kpb = kp + ((size_t)(b * SEQ) * H_ + h) * MMP;
    const float* vb  = v  + ((size_t)(b * SEQ) * H_ + h) * DH_;

    const uint32_t sK = (uint32_t)__cvta_generic_to_shared(&Kp[0][0][0]);
    const uint32_t sV = (uint32_t)__cvta_generic_to_shared(&Vs[0][0][0]);
    const uint32_t kPl = 32 * KPITCH * 2;
    const uint32_t vPl = 32 * VPITCH * 2;

    const int r7 = lane & 7;

    for (int it = 0; it < 8; it++) {
        const int n0 = kc * 256 + it * 32;
        // fill Kp [n][m]
        for (int f = tid; f < 32*68; f += 256) {
            int nn = f / 68, c4 = f % 68;
            float4 vv = *(const float4*)&kpb[(size_t)(n0 + nn) * (H_*MMP) + c4*4];
            uint2 hi, lo;
            splitf4(vv, hi, lo);
            *(uint2*)&Kp[0][nn][c4*4] = hi;
            *(uint2*)&Kp[1][nn][c4*4] = lo;
        }
        // fill Vs [n][e]
        #pragma unroll
        for (int u = 0; u < 2; u++) {
            int f = tid + u * 256;
            int nn = f >> 4, c4 = f & 15;
            float4 vv = *(const float4*)&vb[(size_t)(n0 + nn) * (H_*DH_) + c4*4];
            uint2 hi, lo;
            splitf4(vv, hi, lo);
            *(uint2*)&Vs[0][nn][c4*4] = hi;
            *(uint2*)&Vs[1][nn][c4*4] = lo;
        }
        __syncthreads();

        #pragma unroll
        for (int ks = 0; ks < 2; ks++) {
            // B fragments (v^T) via trans: groups g -> e16
            uint32_t bhf[8][2], blf[8][2];
            #pragma unroll
            for (int g = 0; g < 4; g++) {
                int row = ks*16 + ((lane >> 3) & 1) * 8 + r7;
                int col = g*16 + (lane >> 4) * 8;
                uint32_t addr = sV + (uint32_t)(row * VPITCH + col) * 2;
                uint32_t r[4];
                ldm4t(r, addr);
                bhf[2*g][0] = r[0]; bhf[2*g][1] = r[1];
                bhf[2*g+1][0] = r[2]; bhf[2*g+1][1] = r[3];
                ldm4t(r, addr + vPl);
                blf[2*g][0] = r[0]; blf[2*g][1] = r[1];
                blf[2*g+1][0] = r[2]; blf[2*g+1][1] = r[3];
            }
            #pragma unroll
            for (int t = 0; t < 3; t++) {
                if (t < nmt) {
                    int m0 = mts[t] * 16;
                    int row = ks*16 + ((lane >> 4) & 1) * 8 + r7;
                    int col = m0 + ((lane >> 3) & 1) * 8;
                    uint32_t addr = sK + (uint32_t)(row * KPITCH + col) * 2;
                    uint32_t ah[4], al[4];
                    ldm4t(ah, addr);
                    ldm4t(al, addr + kPl);
                    #pragma unroll
                    for (int nt = 0; nt < 8; nt++) {
                        mma_bf16(acc[t][nt], ah, bhf[nt]);
                        mma_bf16(acc[t][nt], ah, blf[nt]);
                        mma_bf16(acc[t][nt], al, bhf[nt]);
                    }
                }
            }
        }
        __syncthreads();
    }

    // epilogue: part[((bh*8+kc)*272 + m)*64 + e]
    const int gr = lane >> 2;
    const int gc = (lane & 3) * 2;
    float* pb = part + ((size_t)(bh * 8 + kc)) * 272 * 64;
    #pragma unroll
    for (int t = 0; t < 3; t++) {
        if (t < nmt) {
            int m0 = mts[t] * 16;
            #pragma unroll
            for (int nt = 0; nt < 8; nt++) {
                int e = nt*8 + gc;
                pb[(size_t)(m0 + gr) * 64 + e]     = acc[t][nt][0];
                pb[(size_t)(m0 + gr) * 64 + e + 1] = acc[t][nt][1];
                pb[(size_t)(m0 + gr + 8) * 64 + e]     = acc[t][nt][2];
                pb[(size_t)(m0 + gr + 8) * 64 + e + 1] = acc[t][nt][3];
            }
        }
    }
}

// ---------------- reduceT: sum partials, write ctxT[bh][e][m] (+ks row) ----
__global__ void reduceT(const float* __restrict__ part, const float* __restrict__ ks,
                        float* __restrict__ ctxT)
{
    const int bh = blockIdx.y;
    const int m0 = blockIdx.x * 64;
    const int mw = (272 - m0 < 64) ? (272 - m0) : 64;
    __shared__ float sm[64][65];
    const int t = threadIdx.x;
    const int e  = t & 63;
    const int mr = t >> 6;
    for (int mm = mr; mm < mw; mm += 4) {
        float s = 0.f;
        #pragma unroll
        for (int kc = 0; kc < 8; kc++)
            s += part[(((size_t)(bh*8 + kc)) * 272 + m0 + mm) * 64 + e];
        sm[mm][e] = s;
    }
    __syncthreads();
    const int m  = t & 63;
    const int er = t >> 6;
    for (int ee = er; ee < 80; ee += 4) {
        if (m0 + m < 288) {
            float val = 0.f;
            if (m < mw) {
                if (ee < 64)       val = sm[m][ee];
                else if (ee == 64) val = ks[(size_t)bh * MMP + m0 + m];
            }
            ctxT[((size_t)bh * 80 + ee) * 288 + m0 + m] = val;
        }
    }
}

// ======================================================================
// attn_mma: out[bh] = (qp @ ctxT^T) with col 64 = dsum; scale by 1/(dsum+eps)
// M=2048 (n), N=80 (e), K=272 (m). 17 k16 steps.
// ======================================================================
#define APITCH 24
__global__ __launch_bounds__(256, 2)
void attn_mma(const float* __restrict__ qp, const float* __restrict__ ctxT,
              float* __restrict__ out)
{
    __shared__ __align__(16) __nv_bfloat16 As[2][128][APITCH];
    __shared__ __align__(16) __nv_bfloat16 Bs[2][80][APITCH];

    const int tid = threadIdx.x;
    const int lane = tid & 31;
    const int warp = tid >> 5;
    const int bm = blockIdx.x * 128;
    const int bh = blockIdx.y;
    const int b = bh >> 3, h = bh & 7;
    const int wm = warp * 16;

    const float* qpb = qp + ((size_t)(b * SEQ) * H_ + h) * MMP;
    const float* cb  = ctxT + (size_t)bh * 80 * 288;

    float acc[9][4];
    #pragma unroll
    for (int n = 0; n < 9; n++)
        #pragma unroll
        for (int j = 0; j < 4; j++) acc[n][j] = 0.f;

    const uint32_t sA = (uint32_t)__cvta_generic_to_shared(&As[0][0][0]);
    const uint32_t sB = (uint32_t)__cvta_generic_to_shared(&Bs[0][0][0]);
    const uint32_t aPl = 128 * APITCH * 2;
    const uint32_t bPl = 80 * APITCH * 2;
    const int a_m = lane & 15;
    const int a_k = (lane >> 4) << 3;
    const int b_n = (lane & 7) | ((lane & 16) >> 1);
    const int b_k = lane & 8;

    for (int k16 = 0; k16 < 17; k16++) {
        const int k0 = k16 * 16;
        // A fill: 128 rows x 16
        #pragma unroll
        for (int u = 0; u < 2; u++) {
            int f = tid + u * 256;
            int row = f >> 2, c4 = f & 3;
            float4 vv = *(const float4*)&qpb[(size_t)(bm + row) * (H_*MMP) + k0 + c4*4];
            uint2 hi, lo;
            splitf4(vv, hi, lo);
            *(uint2*)&As[0][row][c4*4] = hi;
            *(uint2*)&As[1][row][c4*4] = lo;
        }
        // B fill: 80 rows x 16
        #pragma unroll
        for (int u = 0; u < 2; u++) {
            int f = tid + u * 256;
            if (f < 320) {
                int row = f >> 2, c4 = f & 3;
                float4 vv = *(const float4*)&cb[(size_t)row * 288 + k0 + c4*4];
                uint2 hi, lo;
                splitf4(vv, hi, lo);
                *(uint2*)&Bs[0][row][c4*4] = hi;
                *(uint2*)&Bs[1][row][c4*4] = lo;
            }
        }
        __syncthreads();

        uint32_t bhf[10][2], blf[10][2];
        #pragma unroll
        for (int p = 0; p < 5; p++) {
            uint32_t addr = sB + (uint32_t)((p*16 + b_n) * APITCH + b_k) * 2;
            uint32_t r[4];
            ldm4(r, addr);
            bhf[2*p][0] = r[0]; bhf[2*p][1] = r[1];
            bhf[2*p+1][0] = r[2]; bhf[2*p+1][1] = r[3];
            ldm4(r, addr + bPl);
            blf[2*p][0] = r[0]; blf[2*p][1] = r[1];
            blf[2*p+1][0] = r[2]; blf[2*p+1][1] = r[3];
        }
        {
            uint32_t ah[4], al[4];
            uint32_t addr = sA + (uint32_t)((wm + a_m) * APITCH + a_k) * 2;
            ldm4(ah, addr);
            ldm4(al, addr + aPl);
            #pragma unroll
            for (int nt = 0; nt < 9; nt++) {
                mma_bf16(acc[nt], ah, bhf[nt]);
                mma_bf16(acc[nt], ah, blf[nt]);
                mma_bf16(acc[nt], al, bhf[nt]);
            }
        }
        __syncthreads();
    }

    // dsum (col 64 = nt 8, gc 0, j 0) -> per-row scale
    const int gr = lane >> 2;
    const int gc = (lane & 3) * 2;
    float d0 = __shfl_sync(0xffffffffu, acc[8][0], gr * 4);
    float d1 = __shfl_sync(0xffffffffu, acc[8][2], gr * 4);
    const float dinv0 = 1.f / (d0 + 1e-8f);
    const float dinv1 = 1.f / (d1 + 1e-8f);

    const size_t row0 = ((size_t)(b * SEQ + bm + wm + gr) * H_ + h) * DH_;
    const size_t row1 = row0 + (size_t)8 * H_ * DH_;
    #pragma unroll
    for (int nt = 0; nt < 8; nt++) {
        int e = nt*8 + gc;
        out[row0 + e]     = acc[nt][0] * dinv0;
        out[row0 + e + 1] = acc[nt][1] * dinv0;
        out[row1 + e]     = acc[nt][2] * dinv1;
        out[row1 + e + 1] = acc[nt][3] * dinv1;
    }
}

// ---------------- LayerNorm -----------------
__global__ void ln_kernel(const float* __restrict__ x, const float* __restrict__ g,
                          const float* __restrict__ b, float* __restrict__ out)
{
    const int r = blockIdx.x;
    const int t = threadIdx.x;
    const float4 v = ((const float4*)(x + (size_t)r * D_))[t];
    float s  = v.x + v.y + v.z + v.w;
    float ss = v.x*v.x + v.y*v.y + v.z*v.z + v.w*v.w;
    __shared__ float rs[128], rss[128];
    rs[t] = s; rss[t] = ss;
    __syncthreads();
    for (int o = 64; o > 0; o >>= 1) {
        if (t < o) { rs[t] += rs[t+o]; rss[t] += rss[t+o]; }
        __syncthreads();
    }
    const float mu   = rs[0] * (1.f / D_);
    const float var  = rss[0] * (1.f / D_) - mu * mu;
    const float rstd = rsqrtf(var + 1e-5f);
    const float4 gg = ((const float4*)g)[t];
    const float4 bb = ((const float4*)b)[t];
    float4 o4;
    o4.x = (v.x - mu) * rstd * gg.x + bb.x;
    o4.y = (v.y - mu) * rstd * gg.y + bb.y;
    o4.z = (v.z - mu) * rstd * gg.z + bb.z;
    o4.w = (v.w - mu) * rstd * gg.w + bb.w;
    ((float4*)(out + (size_t)r * D_))[t] = o4;
}

// ---------------- FAVOR postprocess ----
__global__ __launch_bounds__(256)
void favor_post3(float* __restrict__ fp, const float* __restrict__ data, float ratio)
{
    const int lane = threadIdx.x & 31;
    const int w    = threadIdx.x >> 5;
    const size_t rh = (size_t)blockIdx.x * 8 + w;
    const int isQ = rh < (size_t)RH;

    float* prow = fp + rh * MMP;
    const float* drow = data + rh * DH_;

    float2 d2 = ((const float2*)drow)[lane];
    float s = d2.x*d2.x + d2.y*d2.y;
    #pragma unroll
    for (int o = 16; o > 0; o >>= 1) s += __shfl_xor_sync(0xffffffffu, s, o);
    const float diag = s * 0.0625f;

    float v[9];
    #pragma unroll
    for (int j = 0; j < 9; j++) {
        int m = j*32 + lane;
        v[j] = (m < MM) ? prow[m] : -1e30f;
    }

    if (isQ) {
        float mx = v[0];
        #pragma unroll
        for (int j = 1; j < 9; j++) mx = fmaxf(mx, v[j]);
        #pragma unroll
        for (int o = 16; o > 0; o >>= 1) mx = fmaxf(mx, __shfl_xor_sync(0xffffffffu, mx, o));
        #pragma unroll
        for (int j = 0; j < 9; j++) {
            int m = j*32 + lane;
            if (m < MM)       prow[m] = ratio * (expf(v[j] - diag - mx) + 1e-4f);
            else if (m < MMP) prow[m] = 0.f;
        }
    } else {
        #pragma unroll
        for (int j = 0; j < 9; j++) {
            int m = j*32 + lane;
            if (m < MM)       prow[m] = ratio * expf(v[j] - diag + 1e-4f);
            else if (m < MMP) prow[m] = 0.f;
        }
    }
}

// ---------------- ksum two-stage ---------------
__global__ void ksum1(const float* __restrict__ kp, float* __restrict__ part)
{
    const int bh = blockIdx.y;
    const int chunk = blockIdx.x;
    const int m = threadIdx.x;
    if (m >= MMP) return;
    const int b = bh >> 3, h = bh & 7;
    const float* base = kp + ((size_t)(b * SEQ + chunk * 256) * H_ + h) * MMP + m;
    const size_t stride = (size_t)H_ * MMP;
    float s0 = 0.f, s1 = 0.f, s2 = 0.f, s3 = 0.f;
    for (int n = 0; n < 256; n += 4) {
        s0 += base[(n+0) * stride];
        s1 += base[(n+1) * stride];
        s2 += base[(n+2) * stride];
        s3 += base[(n+3) * stride];
    }
    part[((size_t)bh * 8 + chunk) * MMP + m] = (s0 + s1) + (s2 + s3);
}
__global__ void ksum2(const float* __restrict__ part, float* __restrict__ ks)
{
    const int bh = blockIdx.x;
    const int m = threadIdx.x;
    if (m >= MMP) return;
    float s = 0.f;
    #pragma unroll
    for (int c = 0; c < 8; c++) s += part[((size_t)bh * 8 + c) * MMP + m];
    ks[(size_t)bh * MMP + m] = s;
}

// ---------------- depthwise conv + SiLU ---------------
#define DC_CH 128
#define DC_TN 32
__global__ __launch_bounds__(256)
void dwconv2(const float* __restrict__ gin, const float* __restrict__ w,
             const float* __restrict__ bias, float* __restrict__ out)
{
    __shared__ float sin_[DC_TN + 30][DC_CH];
    __shared__ float sw[DC_CH * KW];

    const int c0 = blockIdx.x * DC_CH;
    const int n0 = blockIdx.y * DC_TN;
    const int b  = blockIdx.z;
    const int t  = threadIdx.x;

    for (int i = t; i < DC_CH * KW; i += 256)
        sw[i] = w[(size_t)c0 * KW + i];
    #pragma unroll
    for (int u = 0; u < (DC_TN + 30) * DC_CH / 256; u++) {
        int f = t + u * 256;
        int rowi = f >> 7;
        int ch = f & 127;
        int n = n0 + rowi - 15;
        sin_[rowi][ch] = ((unsigned)n < SEQ)
            ? gin[((size_t)(b * SEQ + n) << 10) + c0 + ch] : 0.f;
    }
    __syncthreads();

    const int ch = t & 127;
    const int nl0 = (t >> 7) * 16;

    float wr[KW];
    #pragma unroll
    for (int k = 0; k < KW; k++) wr[k] = sw[ch * KW + k];
    const float bb = bias[c0 + ch];

    #pragma unroll
    for (int i = 0; i < 16; i++) {
        float acc = bb;
        #pragma unroll
        for (int k = 0; k < KW; k++)
            acc += sin_[nl0 + i + k][ch] * wr[k];
        float o = acc / (1.f + expf(-acc));
        out[((size_t)(b * SEQ + n0 + nl0 + i) << 10) + c0 + ch] = o;
    }
}

// ---------------- host orchestration ----------------------------------------
static inline void run_gemm(const float* A, const uint32_t* Bf, float* C,
                            const float* bias, const float* extra,
                            int Mdim, int Ndim, int Kdim, float alpha, int mode)
{
    dim3 grid((Ndim + 127) / 128, Mdim / 128);
    gemm_tn<<<grid, 256>>>(A, Bf, C, bias, extra, Mdim, Ndim, Kdim, alpha, mode);
}
static inline void run_wfrag(const float* W, uint32_t* out, int Ndim, int Kdim, int NT8)
{
    size_t total = (size_t)NT8 * (Kdim >> 4) * 128;
    wfrag<<<(unsigned)((total + 255) / 256), 256>>>(W, out, Ndim, Kdim, NT8);
}

extern "C" void kernel_launch(void* const* d_in, const int* in_sizes, int n_in,
                              void* d_out, int out_size)
{
    const float* x    = (const float*)d_in[0];
    const float* ln1g = (const float*)d_in[1];
    const float* ln1b = (const float*)d_in[2];
    const float* wq   = (const float*)d_in[3];
    const float* bq   = (const float*)d_in[4];
    const float* wk   = (const float*)d_in[5];
    const float* bk   = (const float*)d_in[6];
    const float* wv   = (const float*)d_in[7];
    const float* bv   = (const float*)d_in[8];
    const float* wo   = (const float*)d_in[9];
    const float* bo   = (const float*)d_in[10];
    const float* proj = (const float*)d_in[11];
    const float* ln2g = (const float*)d_in[12];
    const float* ln2b = (const float*)d_in[13];
    const float* pw1w = (const float*)d_in[14];
    const float* pw1b = (const float*)d_in[15];
    const float* dww  = (const float*)d_in[16];
    const float* dwb  = (const float*)d_in[17];
    const float* pw2w = (const float*)d_in[18];
    const float* pw2b = (const float*)d_in[19];
    float* xo = (float*)d_out;

    float *h, *qkv, *fp, *ks, *part, *cpart, *ctxT, *att, *ya, *glu, *dw, *qkvb;
    uint32_t* wf;
    cudaGetSymbolAddress((void**)&h,     g_h);
    cudaGetSymbolAddress((void**)&qkv,   g_qkv);
    cudaGetSymbolAddress((void**)&fp,    g_fp);
    cudaGetSymbolAddress((void**)&ks,    g_ks);
    cudaGetSymbolAddress((void**)&part,  g_part);
    cudaGetSymbolAddress((void**)&cpart, g_cpart);
    cudaGetSymbolAddress((void**)&ctxT,  g_ctxT);
    cudaGetSymbolAddress((void**)&att,   g_att);
    cudaGetSymbolAddress((void**)&ya,    g_ya);
    cudaGetSymbolAddress((void**)&glu,   g_glu);
    cudaGetSymbolAddress((void**)&dw,    g_dw);
    cudaGetSymbolAddress((void**)&qkvb,  g_qkvbias);
    cudaGetSymbolAddress((void**)&wf,    g_wfrag);

    float* v_buf = qkv + 2 * (size_t)ROWS * ID_;
    float* qp    = fp;
    float* kp    = fp + (size_t)RH * MMP;

    const size_t OFF_WQ = 0;
    const size_t OFF_WO = OFF_WQ + 3*FR_QKV;
    const size_t OFF_P1 = OFF_WO + FR_QKV;
    const size_t OFF_P2 = OFF_P1 + FR_PW1;
    const size_t OFF_PR = OFF_P2 + FR_PW2;

    for (int l = 0; l < LNUM; l++) {
        uint32_t* lw = wf + (size_t)l * FR_LSTR;
        run_wfrag(wq   + (size_t)l*ID_*D_,    lw + OFF_WQ,            512, 512, 64);
        run_wfrag(wk   + (size_t)l*ID_*D_,    lw + OFF_WQ + FR_QKV,   512, 512, 64);
        run_wfrag(wv   + (size_t)l*ID_*D_,    lw + OFF_WQ + 2*FR_QKV, 512, 512, 64);
        run_wfrag(wo   + (size_t)l*ID_*D_,    lw + OFF_WO, 512, 512, 64);
        run_wfrag(pw1w + (size_t)l*2048*D_,   lw + OFF_P1, 2048, 512, 256);
        run_wfrag(pw2w + (size_t)l*D_*INNER_, lw + OFF_P2, 512, 1024, 64);
        run_wfrag(proj + (size_t)l*MM*DH_,    lw + OFF_PR, 266, 64, 48);
    }
    biascat<<<(LNUM*512 + 255)/256, 256>>>(bq, bk, bv, qkvb);

    cudaMemcpyAsync(xo, x, (size_t)ROWS * D_ * sizeof(float),
                    cudaMemcpyDeviceToDevice);

    const float dn    = (float)(1.0 / sqrt(sqrt(64.0)));
    const float ratio = (float)(1.0 / sqrt(266.0));

    for (int l = 0; l < LNUM; l++) {
        uint32_t* lw = wf + (size_t)l * FR_LSTR;

        ln_kernel<<<ROWS, 128>>>(xo, ln1g + (size_t)l*D_, ln1b + (size_t)l*D_, h);
        run_gemm(h, lw + OFF_WQ, qkv, qkvb + (size_t)l*1536, nullptr,
                 ROWS, 1536, D_, 1.f, 3);
        run_gemm(qkv, lw + OFF_PR, qp, nullptr, nullptr, 2*RH, MM, DH_, dn, 1);
        favor_post3<<<2*RH/8, 256>>>(fp, qkv, ratio);
        {
            dim3 k1(8, NBH);
            ksum1<<<k1, 288>>>(kp, part);
            ksum2<<<NBH, 288>>>(part, ks);
            dim3 cg(8, NBH);
            ctx_mma<<<cg, 256>>>(kp, v_buf, cpart);
            dim3 rg(5, NBH);
            reduceT<<<rg, 256>>>(cpart, ks, ctxT);
            dim3 ag(SEQ / 128, NBH);
            attn_mma<<<ag, 256>>>(qp, ctxT, att);
        }
        run_gemm(att, lw + OFF_WO, xo, bo + (size_t)l*D_, xo, ROWS, D_, ID_, 1.f, 0);
        ln_kernel<<<ROWS, 128>>>(xo, ln2g + (size_t)l*D_, ln2b + (size_t)l*D_, h);
        run_gemm(h, lw + OFF_P1, ya, pw1b + (size_t)l*2048, nullptr,
                 ROWS, INNER_, D_, 1.f, 0);
        run_gemm(h, lw + OFF_P1 + (size_t)128*32*128, glu,
                 pw1b + (size_t)l*2048 + INNER_, ya, ROWS, INNER_, D_, 1.f, 2);
        {
            dim3 dg(INNER_/DC_CH, SEQ/DC_TN, B_);
            dwconv2<<<dg, 256>>>(glu, dww + (size_t)l*INNER_*KW, dwb + (size_t)l*INNER_, dw);
        }
        run_gemm(dw, lw + OFF_P2, xo, pw2b + (size_t)l*D_, xo, ROWS, D_, INNER_, 1.f, 0);
    }
}

// round 10
// speedup vs baseline: 1.5598x; 1.0550x over previous
#include <cuda_runtime.h>
#include <cuda_bf16.h>
#include <cuda_fp16.h>
#include <math.h>
#include <stdint.h>

// ---------------- problem constants ----------------
#define B_     4
#define SEQ    2048
#define D_     512
#define H_     8
#define DH_    64
#define ID_    512
#define MM     266
#define MMP    272
#define INNER_ 1024
#define KW     31
#define LNUM   6
#define ROWS   (B_*SEQ)
#define RH     (ROWS*H_)
#define NBH    (B_*H_)

// ---------------- device scratch ----------------
__device__ float g_h    [ROWS*D_];
__device__ float g_qkv  [3*(size_t)ROWS*ID_];   // q | k | v flat [rh][64]
__device__ float g_fp   [2*(size_t)RH*MMP];     // qp | kp flat [rh][272]
__device__ float g_ks   [NBH*MMP];
__device__ float g_part [NBH*8*MMP];
__device__ float g_cpart[(size_t)NBH*8*MMP*DH_]; // ctx partials [bh][kc][272][64]
__device__ float g_ctxT [(size_t)NBH*80*288];    // [bh][e][m]
__device__ float g_att  [ROWS*ID_];
__device__ float g_ya   [ROWS*INNER_];
__device__ float g_glu  [ROWS*INNER_];
__device__ float g_dw   [ROWS*INNER_];
__device__ float g_qkvbias[LNUM*1536];

#define FR_QKV  (64*32*128)
#define FR_PW1  (256*32*128)
#define FR_PW2  (64*64*128)
#define FR_PROJ (48*4*128)
#define FR_LSTR (4*FR_QKV + FR_PW1 + FR_PW2 + FR_PROJ)
__device__ uint32_t g_wfrag[(size_t)LNUM * FR_LSTR];

// ---------------- helpers ----------------
__device__ __forceinline__ uint32_t pk2h(__half a, __half b) {
    __half2 t = __halves2half2(a, b);
    return *reinterpret_cast<uint32_t*>(&t);
}
// fp32x4 -> fp16 hi plane only
__device__ __forceinline__ uint2 cvtf4h(float4 v) {
    uint2 r;
    r.x = pk2h(__float2half_rn(v.x), __float2half_rn(v.y));
    r.y = pk2h(__float2half_rn(v.z), __float2half_rn(v.w));
    return r;
}
// fp32x4 -> fp16 hi + lo planes
__device__ __forceinline__ void splitf4h(float4 v, uint2& hi, uint2& lo) {
    __half h0 = __float2half_rn(v.x), h1 = __float2half_rn(v.y),
           h2 = __float2half_rn(v.z), h3 = __float2half_rn(v.w);
    hi.x = pk2h(h0, h1); hi.y = pk2h(h2, h3);
    lo.x = pk2h(__float2half_rn(v.x - __half2float(h0)),
                __float2half_rn(v.y - __half2float(h1)));
    lo.y = pk2h(__float2half_rn(v.z - __half2float(h2)),
                __float2half_rn(v.w - __half2float(h3)));
}
__device__ __forceinline__ void ldm4(uint32_t* r, uint32_t addr) {
    asm volatile("ldmatrix.sync.aligned.m8n8.x4.shared.b16 {%0,%1,%2,%3}, [%4];\n"
                 : "=r"(r[0]), "=r"(r[1]), "=r"(r[2]), "=r"(r[3]) : "r"(addr));
}
__device__ __forceinline__ void ldm4t(uint32_t* r, uint32_t addr) {
    asm volatile("ldmatrix.sync.aligned.m8n8.x4.trans.shared.b16 {%0,%1,%2,%3}, [%4];\n"
                 : "=r"(r[0]), "=r"(r[1]), "=r"(r[2]), "=r"(r[3]) : "r"(addr));
}
__device__ __forceinline__ void mma_f16(float* c, const uint32_t* a, const uint32_t* b) {
    asm volatile(
        "mma.sync.aligned.m16n8k16.row.col.f32.f16.f16.f32 "
        "{%0,%1,%2,%3}, {%4,%5,%6,%7}, {%8,%9}, {%0,%1,%2,%3};\n"
        : "+f"(c[0]), "+f"(c[1]), "+f"(c[2]), "+f"(c[3])
        : "r"(a[0]), "r"(a[1]), "r"(a[2]), "r"(a[3]), "r"(b[0]), "r"(b[1]));
}

// ---------------- weight -> fragment converter (fp16 hi/lo) -----------------
__global__ void wfrag(const float* __restrict__ W, uint32_t* __restrict__ out,
                      int Ndim, int Kdim, int NT8)
{
    const int KT16 = Kdim >> 4;
    size_t idx = (size_t)blockIdx.x * 256 + threadIdx.x;
    size_t total = (size_t)NT8 * KT16 * 128;
    if (idx >= total) return;
    int r     = (int)(idx & 1);
    int l     = (int)((idx >> 1) & 31);
    int plane = (int)((idx >> 6) & 1);
    size_t ft = idx >> 7;
    int k16 = (int)(ft % KT16);
    int n8  = (int)(ft / KT16);
    int n = n8 * 8 + (l >> 2);
    int k = k16 * 16 + (l & 3) * 2 + r * 8;
    float v0 = 0.f, v1 = 0.f;
    if (n < Ndim) {
        float2 vv = *(const float2*)&W[(size_t)n * Kdim + k];
        v0 = vv.x; v1 = vv.y;
    }
    __half h0 = __float2half_rn(v0), h1 = __float2half_rn(v1);
    uint32_t val = (plane == 0)
        ? pk2h(h0, h1)
        : pk2h(__float2half_rn(v0 - __half2float(h0)),
               __float2half_rn(v1 - __half2float(h1)));
    out[idx] = val;
}

__global__ void biascat(const float* __restrict__ bq, const float* __restrict__ bk,
                        const float* __restrict__ bv, float* __restrict__ out)
{
    int i = blockIdx.x * 256 + threadIdx.x;
    if (i < LNUM * 512) {
        int l = i >> 9, c = i & 511;
        out[l*1536 + c]        = bq[i];
        out[l*1536 + 512 + c]  = bk[i];
        out[l*1536 + 1024 + c] = bv[i];
    }
}

// ======================================================================
// main GEMM: A fp16 (optionally split), B = weight fragments hi/lo fp16.
// modes: 0 normal(+resid), 1 [rh][MMP] out, 2 gate, 3 qkv split
// ======================================================================
#define ASTR 40
#define PLANE_ELEMS (128*ASTR)
#define PLANE_BYTES (PLANE_ELEMS*2)

__global__ __launch_bounds__(256, 2)
void gemm_tn(const float* __restrict__ A, const uint32_t* __restrict__ Bf,
             float* __restrict__ C, const float* __restrict__ bias,
             const float* __restrict__ extra,
             int Mdim, int Ndim, int Kdim, float alpha, int mode, int split_a)
{
    __shared__ __align__(16) __half Asm[2][128][ASTR];

    const int tid  = threadIdx.x;
    const int lane = tid & 31;
    const int warp = tid >> 5;
    const int wm = (warp & 1) * 64;
    const int wn = (warp >> 1) * 32;
    const int bm = blockIdx.y * 128;
    const int bn = blockIdx.x * 128;
    const int KT16 = Kdim >> 4;
    const int n8_0 = (bn + wn) >> 3;

    const int r0 = tid >> 3;
    const int kk = (tid & 7) * 4;

    float acc[4][4][4];
    #pragma unroll
    for (int i = 0; i < 4; i++)
        #pragma unroll
        for (int j = 0; j < 4; j++)
            #pragma unroll
            for (int t = 0; t < 4; t++) acc[i][j][t] = 0.f;

    const int a_m = lane & 15;
    const int a_k = (lane >> 4) << 3;
    const uint32_t sA = (uint32_t)__cvta_generic_to_shared(&Asm[0][0][0]);

    const int KT = Kdim >> 5;
    for (int kt = 0; kt < KT; kt++) {
        #pragma unroll
        for (int u = 0; u < 4; u++) {
            const int row = r0 + u * 32;
            float4 v = *(const float4*)&A[(size_t)(bm + row) * Kdim + kt*32 + kk];
            if (split_a) {
                uint2 hi, lo;
                splitf4h(v, hi, lo);
                *(uint2*)&Asm[0][row][kk] = hi;
                *(uint2*)&Asm[1][row][kk] = lo;
            } else {
                *(uint2*)&Asm[0][row][kk] = cvtf4h(v);
            }
        }
        __syncthreads();

        #pragma unroll
        for (int ks = 0; ks < 2; ks++) {
            uint32_t bhf[4][2], blf[4][2];
            const uint32_t* fb = Bf + ((size_t)n8_0 * KT16 + (kt*2 + ks)) * 128 + lane * 2;
            #pragma unroll
            for (int nt = 0; nt < 4; nt++) {
                const uint32_t* fp2 = fb + (size_t)nt * KT16 * 128;
                uint2 h  = *(const uint2*)fp2;
                uint2 lo = *(const uint2*)(fp2 + 64);
                bhf[nt][0] = h.x;  bhf[nt][1] = h.y;
                blf[nt][0] = lo.x; blf[nt][1] = lo.y;
            }
            #pragma unroll
            for (int mt = 0; mt < 4; mt++) {
                uint32_t ah[4];
                uint32_t addr = sA + (uint32_t)(((wm + mt*16 + a_m) * ASTR) + ks*16 + a_k) * 2;
                ldm4(ah, addr);
                #pragma unroll
                for (int nt = 0; nt < 4; nt++) {
                    mma_f16(acc[mt][nt], ah, bhf[nt]);
                    mma_f16(acc[mt][nt], ah, blf[nt]);
                }
                if (split_a) {
                    uint32_t al[4];
                    ldm4(al, addr + PLANE_BYTES);
                    #pragma unroll
                    for (int nt = 0; nt < 4; nt++)
                        mma_f16(acc[mt][nt], al, bhf[nt]);
                }
            }
        }
        __syncthreads();
    }

    const int gr = lane >> 2;
    const int gc = (lane & 3) * 2;
    #pragma unroll
    for (int mt = 0; mt < 4; mt++) {
        #pragma unroll
        for (int nt = 0; nt < 4; nt++) {
            const float* cp = acc[mt][nt];
            int row = bm + wm + mt*16 + gr;
            int col = bn + wn + nt*8 + gc;
            #pragma unroll
            for (int half = 0; half < 2; half++) {
                int rr = row + half*8;
                #pragma unroll
                for (int j = 0; j < 2; j++) {
                    int cc = col + j;
                    if (cc < Ndim) {
                        float val = cp[half*2 + j] * alpha;
                        if (bias) val += bias[cc];
                        if (mode == 0) {
                            if (extra) val += extra[(size_t)rr * Ndim + cc];
                            C[(size_t)rr * Ndim + cc] = val;
                        } else if (mode == 1) {
                            C[(size_t)rr * MMP + cc] = val;
                        } else if (mode == 2) {
                            float a = extra[(size_t)rr * Ndim + cc];
                            C[(size_t)rr * Ndim + cc] = a / (1.f + expf(-val));
                        } else {
                            C[(size_t)(cc >> 9) * ((size_t)ROWS * ID_)
                              + (size_t)rr * ID_ + (cc & 511)] = val;
                        }
                    }
                }
            }
        }
    }
}

// ======================================================================
// ctx_mma: partial ctx[bh] = kp^T @ v over 256-seq chunk.
// A = kp^T fp16 single plane; B = v^T fp16 hi/lo (split).
// ======================================================================
#define KPITCH 280
#define VPITCH 72
__global__ __launch_bounds__(256, 1)
void ctx_mma(const float* __restrict__ kp, const float* __restrict__ v,
             float* __restrict__ part)
{
    __shared__ __align__(16) __half Kp[32][KPITCH];
    __shared__ __align__(16) __half Vs[2][32][VPITCH];

    const int tid = threadIdx.x;
    const int lane = tid & 31;
    const int warp = tid >> 5;
    const int kc = blockIdx.x;
    const int bh = blockIdx.y;
    const int b = bh >> 3, h = bh & 7;

    const int nmt = (warp == 0) ? 3 : 2;
    int mts[3];
    mts[0] = 2*warp; mts[1] = 2*warp + 1; mts[2] = 16;

    float acc[3][8][4];
    #pragma unroll
    for (int t = 0; t < 3; t++)
        #pragma unroll
        for (int n = 0; n < 8; n++)
            #pragma unroll
            for (int j = 0; j < 4; j++) acc[t][n][j] = 0.f;

    const float* kpb = kp + ((size_t)(b * SEQ) * H_ + h) * MMP;
    const float* vb  = v  + ((size_t)(b * SEQ) * H_ + h) * DH_;

    const uint32_t sK = (uint32_t)__cvta_generic_to_shared(&Kp[0][0]);
    const uint32_t sV = (uint32_t)__cvta_generic_to_shared(&Vs[0][0][0]);
    const uint32_t vPl = 32 * VPITCH * 2;

    const int r7 = lane & 7;

    for (int it = 0; it < 8; it++) {
        const int n0 = kc * 256 + it * 32;
        // fill Kp [n][m] (fp16 hi only)
        for (int f = tid; f < 32*68; f += 256) {
            int nn = f / 68, c4 = f % 68;
            float4 vv = *(const float4*)&kpb[(size_t)(n0 + nn) * (H_*MMP) + c4*4];
            *(uint2*)&Kp[nn][c4*4] = cvtf4h(vv);
        }
        // fill Vs [n][e] (hi/lo)
        #pragma unroll
        for (int u = 0; u < 2; u++) {
            int f = tid + u * 256;
            int nn = f >> 4, c4 = f & 15;
            float4 vv = *(const float4*)&vb[(size_t)(n0 + nn) * (H_*DH_) + c4*4];
            uint2 hi, lo;
            splitf4h(vv, hi, lo);
            *(uint2*)&Vs[0][nn][c4*4] = hi;
            *(uint2*)&Vs[1][nn][c4*4] = lo;
        }
        __syncthreads();

        #pragma unroll
        for (int ks = 0; ks < 2; ks++) {
            uint32_t bhf[8][2], blf[8][2];
            #pragma unroll
            for (int g = 0; g < 4; g++) {
                int row = ks*16 + ((lane >> 3) & 1) * 8 + r7;
                int col = g*16 + (lane >> 4) * 8;
                uint32_t addr = sV + (uint32_t)(row * VPITCH + col) * 2;
                uint32_t r[4];
                ldm4t(r, addr);
                bhf[2*g][0] = r[0]; bhf[2*g][1] = r[1];
                bhf[2*g+1][0] = r[2]; bhf[2*g+1][1] = r[3];
                ldm4t(r, addr + vPl);
                blf[2*g][0] = r[0]; blf[2*g][1] = r[1];
                blf[2*g+1][0] = r[2]; blf[2*g+1][1] = r[3];
            }
            #pragma unroll
            for (int t = 0; t < 3; t++) {
                if (t < nmt) {
                    int m0 = mts[t] * 16;
                    int row = ks*16 + ((lane >> 4) & 1) * 8 + r7;
                    int col = m0 + ((lane >> 3) & 1) * 8;
                    uint32_t addr = sK + (uint32_t)(row * KPITCH + col) * 2;
                    uint32_t ah[4];
                    ldm4t(ah, addr);
                    #pragma unroll
                    for (int nt = 0; nt < 8; nt++) {
                        mma_f16(acc[t][nt], ah, bhf[nt]);
                        mma_f16(acc[t][nt], ah, blf[nt]);
                    }
                }
            }
        }
        __syncthreads();
    }

    const int gr = lane >> 2;
    const int gc = (lane & 3) * 2;
    float* pb = part + ((size_t)(bh * 8 + kc)) * 272 * 64;
    #pragma unroll
    for (int t = 0; t < 3; t++) {
        if (t < nmt) {
            int m0 = mts[t] * 16;
            #pragma unroll
            for (int nt = 0; nt < 8; nt++) {
                int e = nt*8 + gc;
                pb[(size_t)(m0 + gr) * 64 + e]     = acc[t][nt][0];
                pb[(size_t)(m0 + gr) * 64 + e + 1] = acc[t][nt][1];
                pb[(size_t)(m0 + gr + 8) * 64 + e]     = acc[t][nt][2];
                pb[(size_t)(m0 + gr + 8) * 64 + e + 1] = acc[t][nt][3];
            }
        }
    }
}

// ---------------- reduceT: sum partials, write ctxT[bh][e][m] (+ks row) ----
__global__ void reduceT(const float* __restrict__ part, const float* __restrict__ ks,
                        float* __restrict__ ctxT)
{
    const int bh = blockIdx.y;
    const int m0 = blockIdx.x * 64;
    const int mw = (272 - m0 < 64) ? (272 - m0) : 64;
    __shared__ float sm[64][65];
    const int t = threadIdx.x;
    const int e  = t & 63;
    const int mr = t >> 6;
    for (int mm = mr; mm < mw; mm += 4) {
        float s = 0.f;
        #pragma unroll
        for (int kc = 0; kc < 8; kc++)
            s += part[(((size_t)(bh*8 + kc)) * 272 + m0 + mm) * 64 + e];
        sm[mm][e] = s;
    }
    __syncthreads();
    const int m  = t & 63;
    const int er = t >> 6;
    for (int ee = er; ee < 80; ee += 4) {
        if (m0 + m < 288) {
            float val = 0.f;
            if (m < mw) {
                if (ee < 64)       val = sm[m][ee];
                else if (ee == 64) val = ks[(size_t)bh * MMP + m0 + m];
            }
            ctxT[((size_t)bh * 80 + ee) * 288 + m0 + m] = val;
        }
    }
}

// ======================================================================
// attn_mma: out = qp @ ctxT^T ; col 64 = dsum; scale by 1/(dsum+eps)
// A = qp fp16 single; B = ctxT fp16 hi/lo.
// ======================================================================
#define APITCH 24
__global__ __launch_bounds__(256, 2)
void attn_mma(const float* __restrict__ qp, const float* __restrict__ ctxT,
              float* __restrict__ out)
{
    __shared__ __align__(16) __half As[128][APITCH];
    __shared__ __align__(16) __half Bs[2][80][APITCH];

    const int tid = threadIdx.x;
    const int lane = tid & 31;
    const int warp = tid >> 5;
    const int bm = blockIdx.x * 128;
    const int bh = blockIdx.y;
    const int b = bh >> 3, h = bh & 7;
    const int wm = warp * 16;

    const float* qpb = qp + ((size_t)(b * SEQ) * H_ + h) * MMP;
    const float* cb  = ctxT + (size_t)bh * 80 * 288;

    float acc[9][4];
    #pragma unroll
    for (int n = 0; n < 9; n++)
        #pragma unroll
        for (int j = 0; j < 4; j++) acc[n][j] = 0.f;

    const uint32_t sA = (uint32_t)__cvta_generic_to_shared(&As[0][0]);
    const uint32_t sB = (uint32_t)__cvta_generic_to_shared(&Bs[0][0][0]);
    const uint32_t bPl = 80 * APITCH * 2;
    const int a_m = lane & 15;
    const int a_k = (lane >> 4) << 3;
    const int b_n = (lane & 7) | ((lane & 16) >> 1);
    const int b_k = lane & 8;

    for (int k16 = 0; k16 < 17; k16++) {
        const int k0 = k16 * 16;
        #pragma unroll
        for (int u = 0; u < 2; u++) {
            int f = tid + u * 256;
            int row = f >> 2, c4 = f & 3;
            float4 vv = *(const float4*)&qpb[(size_t)(bm + row) * (H_*MMP) + k0 + c4*4];
            *(uint2*)&As[row][c4*4] = cvtf4h(vv);
        }
        #pragma unroll
        for (int u = 0; u < 2; u++) {
            int f = tid + u * 256;
            if (f < 320) {
                int row = f >> 2, c4 = f & 3;
                float4 vv = *(const float4*)&cb[(size_t)row * 288 + k0 + c4*4];
                uint2 hi, lo;
                splitf4h(vv, hi, lo);
                *(uint2*)&Bs[0][row][c4*4] = hi;
                *(uint2*)&Bs[1][row][c4*4] = lo;
            }
        }
        __syncthreads();

        uint32_t bhf[10][2], blf[10][2];
        #pragma unroll
        for (int p = 0; p < 5; p++) {
            uint32_t addr = sB + (uint32_t)((p*16 + b_n) * APITCH + b_k) * 2;
            uint32_t r[4];
            ldm4(r, addr);
            bhf[2*p][0] = r[0]; bhf[2*p][1] = r[1];
            bhf[2*p+1][0] = r[2]; bhf[2*p+1][1] = r[3];
            ldm4(r, addr + bPl);
            blf[2*p][0] = r[0]; blf[2*p][1] = r[1];
            blf[2*p+1][0] = r[2]; blf[2*p+1][1] = r[3];
        }
        {
            uint32_t ah[4];
            uint32_t addr = sA + (uint32_t)((wm + a_m) * APITCH + a_k) * 2;
            ldm4(ah, addr);
            #pragma unroll
            for (int nt = 0; nt < 9; nt++) {
                mma_f16(acc[nt], ah, bhf[nt]);
                mma_f16(acc[nt], ah, blf[nt]);
            }
        }
        __syncthreads();
    }

    const int gr = lane >> 2;
    const int gc = (lane & 3) * 2;
    float d0 = __shfl_sync(0xffffffffu, acc[8][0], gr * 4);
    float d1 = __shfl_sync(0xffffffffu, acc[8][2], gr * 4);
    const float dinv0 = 1.f / (d0 + 1e-8f);
    const float dinv1 = 1.f / (d1 + 1e-8f);

    const size_t row0 = ((size_t)(b * SEQ + bm + wm + gr) * H_ + h) * DH_;
    const size_t row1 = row0 + (size_t)8 * H_ * DH_;
    #pragma unroll
    for (int nt = 0; nt < 8; nt++) {
        int e = nt*8 + gc;
        out[row0 + e]     = acc[nt][0] * dinv0;
        out[row0 + e + 1] = acc[nt][1] * dinv0;
        out[row1 + e]     = acc[nt][2] * dinv1;
        out[row1 + e + 1] = acc[nt][3] * dinv1;
    }
}

// ---------------- LayerNorm -----------------
__global__ void ln_kernel(const float* __restrict__ x, const float* __restrict__ g,
                          const float* __restrict__ b, float* __restrict__ out)
{
    const int r = blockIdx.x;
    const int t = threadIdx.x;
    const float4 v = ((const float4*)(x + (size_t)r * D_))[t];
    float s  = v.x + v.y + v.z + v.w;
    float ss = v.x*v.x + v.y*v.y + v.z*v.z + v.w*v.w;
    __shared__ float rs[128], rss[128];
    rs[t] = s; rss[t] = ss;
    __syncthreads();
    for (int o = 64; o > 0; o >>= 1) {
        if (t < o) { rs[t] += rs[t+o]; rss[t] += rss[t+o]; }
        __syncthreads();
    }
    const float mu   = rs[0] * (1.f / D_);
    const float var  = rss[0] * (1.f / D_) - mu * mu;
    const float rstd = rsqrtf(var + 1e-5f);
    const float4 gg = ((const float4*)g)[t];
    const float4 bb = ((const float4*)b)[t];
    float4 o4;
    o4.x = (v.x - mu) * rstd * gg.x + bb.x;
    o4.y = (v.y - mu) * rstd * gg.y + bb.y;
    o4.z = (v.z - mu) * rstd * gg.z + bb.z;
    o4.w = (v.w - mu) * rstd * gg.w + bb.w;
    ((float4*)(out + (size_t)r * D_))[t] = o4;
}

// ---------------- FAVOR postprocess ----
__global__ __launch_bounds__(256)
void favor_post3(float* __restrict__ fp, const float* __restrict__ data, float ratio)
{
    const int lane = threadIdx.x & 31;
    const int w    = threadIdx.x >> 5;
    const size_t rh = (size_t)blockIdx.x * 8 + w;
    const int isQ = rh < (size_t)RH;

    float* prow = fp + rh * MMP;
    const float* drow = data + rh * DH_;

    float2 d2 = ((const float2*)drow)[lane];
    float s = d2.x*d2.x + d2.y*d2.y;
    #pragma unroll
    for (int o = 16; o > 0; o >>= 1) s += __shfl_xor_sync(0xffffffffu, s, o);
    const float diag = s * 0.0625f;

    float v[9];
    #pragma unroll
    for (int j = 0; j < 9; j++) {
        int m = j*32 + lane;
        v[j] = (m < MM) ? prow[m] : -1e30f;
    }

    if (isQ) {
        float mx = v[0];
        #pragma unroll
        for (int j = 1; j < 9; j++) mx = fmaxf(mx, v[j]);
        #pragma unroll
        for (int o = 16; o > 0; o >>= 1) mx = fmaxf(mx, __shfl_xor_sync(0xffffffffu, mx, o));
        #pragma unroll
        for (int j = 0; j < 9; j++) {
            int m = j*32 + lane;
            if (m < MM)       prow[m] = ratio * (expf(v[j] - diag - mx) + 1e-4f);
            else if (m < MMP) prow[m] = 0.f;
        }
    } else {
        #pragma unroll
        for (int j = 0; j < 9; j++) {
            int m = j*32 + lane;
            if (m < MM)       prow[m] = ratio * expf(v[j] - diag + 1e-4f);
            else if (m < MMP) prow[m] = 0.f;
        }
    }
}

// ---------------- ksum two-stage ---------------
__global__ void ksum1(const float* __restrict__ kp, float* __restrict__ part)
{
    const int bh = blockIdx.y;
    const int chunk = blockIdx.x;
    const int m = threadIdx.x;
    if (m >= MMP) return;
    const int b = bh >> 3, h = bh & 7;
    const float* base = kp + ((size_t)(b * SEQ + chunk * 256) * H_ + h) * MMP + m;
    const size_t stride = (size_t)H_ * MMP;
    float s0 = 0.f, s1 = 0.f, s2 = 0.f, s3 = 0.f;
    for (int n = 0; n < 256; n += 4) {
        s0 += base[(n+0) * stride];
        s1 += base[(n+1) * stride];
        s2 += base[(n+2) * stride];
        s3 += base[(n+3) * stride];
    }
    part[((size_t)bh * 8 + chunk) * MMP + m] = (s0 + s1) + (s2 + s3);
}
__global__ void ksum2(const float* __restrict__ part, float* __restrict__ ks)
{
    const int bh = blockIdx.x;
    const int m = threadIdx.x;
    if (m >= MMP) return;
    float s = 0.f;
    #pragma unroll
    for (int c = 0; c < 8; c++) s += part[((size_t)bh * 8 + c) * MMP + m];
    ks[(size_t)bh * MMP + m] = s;
}

// ---------------- depthwise conv + SiLU ---------------
#define DC_CH 128
#define DC_TN 32
__global__ __launch_bounds__(256)
void dwconv2(const float* __restrict__ gin, const float* __restrict__ w,
             const float* __restrict__ bias, float* __restrict__ out)
{
    __shared__ float sin_[DC_TN + 30][DC_CH];
    __shared__ float sw[DC_CH * KW];

    const int c0 = blockIdx.x * DC_CH;
    const int n0 = blockIdx.y * DC_TN;
    const int b  = blockIdx.z;
    const int t  = threadIdx.x;

    for (int i = t; i < DC_CH * KW; i += 256)
        sw[i] = w[(size_t)c0 * KW + i];
    #pragma unroll
    for (int u = 0; u < (DC_TN + 30) * DC_CH / 256; u++) {
        int f = t + u * 256;
        int rowi = f >> 7;
        int ch = f & 127;
        int n = n0 + rowi - 15;
        sin_[rowi][ch] = ((unsigned)n < SEQ)
            ? gin[((size_t)(b * SEQ + n) << 10) + c0 + ch] : 0.f;
    }
    __syncthreads();

    const int ch = t & 127;
    const int nl0 = (t >> 7) * 16;

    float wr[KW];
    #pragma unroll
    for (int k = 0; k < KW; k++) wr[k] = sw[ch * KW + k];
    const float bb = bias[c0 + ch];

    #pragma unroll
    for (int i = 0; i < 16; i++) {
        float acc = bb;
        #pragma unroll
        for (int k = 0; k < KW; k++)
            acc += sin_[nl0 + i + k][ch] * wr[k];
        float o = acc / (1.f + expf(-acc));
        out[((size_t)(b * SEQ + n0 + nl0 + i) << 10) + c0 + ch] = o;
    }
}

// ---------------- host orchestration ----------------------------------------
static inline void run_gemm(const float* A, const uint32_t* Bf, float* C,
                            const float* bias, const float* extra,
                            int Mdim, int Ndim, int Kdim, float alpha, int mode,
                            int split_a)
{
    dim3 grid((Ndim + 127) / 128, Mdim / 128);
    gemm_tn<<<grid, 256>>>(A, Bf, C, bias, extra, Mdim, Ndim, Kdim, alpha, mode, split_a);
}
static inline void run_wfrag(const float* W, uint32_t* out, int Ndim, int Kdim, int NT8)
{
    size_t total = (size_t)NT8 * (Kdim >> 4) * 128;
    wfrag<<<(unsigned)((total + 255) / 256), 256>>>(W, out, Ndim, Kdim, NT8);
}

extern "C" void kernel_launch(void* const* d_in, const int* in_sizes, int n_in,
                              void* d_out, int out_size)
{
    const float* x    = (const float*)d_in[0];
    const float* ln1g = (const float*)d_in[1];
    const float* ln1b = (const float*)d_in[2];
    const float* wq   = (const float*)d_in[3];
    const float* bq   = (const float*)d_in[4];
    const float* wk   = (const float*)d_in[5];
    const float* bk   = (const float*)d_in[6];
    const float* wv   = (const float*)d_in[7];
    const float* bv   = (const float*)d_in[8];
    const float* wo   = (const float*)d_in[9];
    const float* bo   = (const float*)d_in[10];
    const float* proj = (const float*)d_in[11];
    const float* ln2g = (const float*)d_in[12];
    const float* ln2b = (const float*)d_in[13];
    const float* pw1w = (const float*)d_in[14];
    const float* pw1b = (const float*)d_in[15];
    const float* dww  = (const float*)d_in[16];
    const float* dwb  = (const float*)d_in[17];
    const float* pw2w = (const float*)d_in[18];
    const float* pw2b = (const float*)d_in[19];
    float* xo = (float*)d_out;

    float *h, *qkv, *fp, *ks, *part, *cpart, *ctxT, *att, *ya, *glu, *dw, *qkvb;
    uint32_t* wf;
    cudaGetSymbolAddress((void**)&h,     g_h);
    cudaGetSymbolAddress((void**)&qkv,   g_qkv);
    cudaGetSymbolAddress((void**)&fp,    g_fp);
    cudaGetSymbolAddress((void**)&ks,    g_ks);
    cudaGetSymbolAddress((void**)&part,  g_part);
    cudaGetSymbolAddress((void**)&cpart, g_cpart);
    cudaGetSymbolAddress((void**)&ctxT,  g_ctxT);
    cudaGetSymbolAddress((void**)&att,   g_att);
    cudaGetSymbolAddress((void**)&ya,    g_ya);
    cudaGetSymbolAddress((void**)&glu,   g_glu);
    cudaGetSymbolAddress((void**)&dw,    g_dw);
    cudaGetSymbolAddress((void**)&qkvb,  g_qkvbias);
    cudaGetSymbolAddress((void**)&wf,    g_wfrag);

    float* v_buf = qkv + 2 * (size_t)ROWS * ID_;
    float* qp    = fp;
    float* kp    = fp + (size_t)RH * MMP;

    const size_t OFF_WQ = 0;
    const size_t OFF_WO = OFF_WQ + 3*FR_QKV;
    const size_t OFF_P1 = OFF_WO + FR_QKV;
    const size_t OFF_P2 = OFF_P1 + FR_PW1;
    const size_t OFF_PR = OFF_P2 + FR_PW2;

    for (int l = 0; l < LNUM; l++) {
        uint32_t* lw = wf + (size_t)l * FR_LSTR;
        run_wfrag(wq   + (size_t)l*ID_*D_,    lw + OFF_WQ,            512, 512, 64);
        run_wfrag(wk   + (size_t)l*ID_*D_,    lw + OFF_WQ + FR_QKV,   512, 512, 64);
        run_wfrag(wv   + (size_t)l*ID_*D_,    lw + OFF_WQ + 2*FR_QKV, 512, 512, 64);
        run_wfrag(wo   + (size_t)l*ID_*D_,    lw + OFF_WO, 512, 512, 64);
        run_wfrag(pw1w + (size_t)l*2048*D_,   lw + OFF_P1, 2048, 512, 256);
        run_wfrag(pw2w + (size_t)l*D_*INNER_, lw + OFF_P2, 512, 1024, 64);
        run_wfrag(proj + (size_t)l*MM*DH_,    lw + OFF_PR, 266, 64, 48);
    }
    biascat<<<(LNUM*512 + 255)/256, 256>>>(bq, bk, bv, qkvb);

    cudaMemcpyAsync(xo, x, (size_t)ROWS * D_ * sizeof(float),
                    cudaMemcpyDeviceToDevice);

    const float dn    = (float)(1.0 / sqrt(sqrt(64.0)));
    const float ratio = (float)(1.0 / sqrt(266.0));

    for (int l = 0; l < LNUM; l++) {
        uint32_t* lw = wf + (size_t)l * FR_LSTR;

        ln_kernel<<<ROWS, 128>>>(xo, ln1g + (size_t)l*D_, ln1b + (size_t)l*D_, h);
        run_gemm(h, lw + OFF_WQ, qkv, qkvb + (size_t)l*1536, nullptr,
                 ROWS, 1536, D_, 1.f, 3, 0);
        // feature-map GEMM feeds exp(): keep 3-term (split A)
        run_gemm(qkv, lw + OFF_PR, qp, nullptr, nullptr, 2*RH, MM, DH_, dn, 1, 1);
        favor_post3<<<2*RH/8, 256>>>(fp, qkv, ratio);
        {
            dim3 k1(8, NBH);
            ksum1<<<k1, 288>>>(kp, part);
            ksum2<<<NBH, 288>>>(part, ks);
            dim3 cg(8, NBH);
            ctx_mma<<<cg, 256>>>(kp, v_buf, cpart);
            dim3 rg(5, NBH);
            reduceT<<<rg, 256>>>(cpart, ks, ctxT);
            dim3 ag(SEQ / 128, NBH);
            attn_mma<<<ag, 256>>>(qp, ctxT, att);
        }
        run_gemm(att, lw + OFF_WO, xo, bo + (size_t)l*D_, xo, ROWS, D_, ID_, 1.f, 0, 0);
        ln_kernel<<<ROWS, 128>>>(xo, ln2g + (size_t)l*D_, ln2b + (size_t)l*D_, h);
        run_gemm(h, lw + OFF_P1, ya, pw1b + (size_t)l*2048, nullptr,
                 ROWS, INNER_, D_, 1.f, 0, 0);
        run_gemm(h, lw + OFF_P1 + (size_t)128*32*128, glu,
                 pw1b + (size_t)l*2048 + INNER_, ya, ROWS, INNER_, D_, 1.f, 2, 0);
        {
            dim3 dg(INNER_/DC_CH, SEQ/DC_TN, B_);
            dwconv2<<<dg, 256>>>(glu, dww + (size_t)l*INNER_*KW, dwb + (size_t)l*INNER_, dw);
        }
        run_gemm(dw, lw + OFF_P2, xo, pw2b + (size_t)l*D_, xo, ROWS, D_, INNER_, 1.f, 0, 0);
    }
}

// round 11
// speedup vs baseline: 2.4264x; 1.5556x over previous
#include <cuda_runtime.h>
#include <cuda_fp16.h>
#include <math.h>
#include <stdint.h>

// ---------------- problem constants ----------------
#define B_     4
#define SEQ    2048
#define D_     512
#define H_     8
#define DH_    64
#define ID_    512
#define MM     266
#define MMP    272
#define INNER_ 1024
#define KW     31
#define LNUM   6
#define ROWS   (B_*SEQ)
#define RH     (ROWS*H_)
#define NBH    (B_*H_)

// ---------------- device scratch ----------------
__device__ __half g_h   [ROWS*D_];                 // LN out (GEMM A only)
__device__ float  g_qk  [2*(size_t)ROWS*ID_];      // q | k fp32 (favor + proj A)
__device__ __half g_vh  [ROWS*ID_];                // v fp16 (ctx B)
__device__ float  g_fp  [2*(size_t)RH*MMP];        // proj out fp32
__device__ __half g_fph [2*(size_t)RH*MMP];        // qp | kp fp16
__device__ float  g_ks  [NBH*MMP];
__device__ float  g_part[NBH*8*MMP];
__device__ float  g_cpart[(size_t)NBH*8*MMP*DH_];  // ctx partials fp32
__device__ __half g_ctxT[(size_t)NBH*80*288];      // [bh][e][m] fp16
__device__ __half g_att [ROWS*ID_];                // attn out fp16 (wo A)
__device__ float  g_ya  [ROWS*INNER_];             // pw1 'a' half fp32
__device__ __half g_glu [ROWS*INNER_];             // gated, fp16 (dwconv in)
__device__ __half g_dw  [ROWS*INNER_];             // dwconv out fp16 (pw2 A)
__device__ float  g_qkvbias[LNUM*1536];

#define FR_QKV  (64*32*128)
#define FR_PW1  (256*32*128)
#define FR_PW2  (64*64*128)
#define FR_PROJ (48*4*128)
#define FR_LSTR (4*FR_QKV + FR_PW1 + FR_PW2 + FR_PROJ)
__device__ uint32_t g_wfrag[(size_t)LNUM * FR_LSTR];

// ---------------- helpers ----------------
__device__ __forceinline__ uint32_t pk2h(__half a, __half b) {
    __half2 t = __halves2half2(a, b);
    return *reinterpret_cast<uint32_t*>(&t);
}
__device__ __forceinline__ void splitf4h(float4 v, uint2& hi, uint2& lo) {
    __half h0 = __float2half_rn(v.x), h1 = __float2half_rn(v.y),
           h2 = __float2half_rn(v.z), h3 = __float2half_rn(v.w);
    hi.x = pk2h(h0, h1); hi.y = pk2h(h2, h3);
    lo.x = pk2h(__float2half_rn(v.x - __half2float(h0)),
                __float2half_rn(v.y - __half2float(h1)));
    lo.y = pk2h(__float2half_rn(v.z - __half2float(h2)),
                __float2half_rn(v.w - __half2float(h3)));
}
__device__ __forceinline__ void ldm4(uint32_t* r, uint32_t addr) {
    asm volatile("ldmatrix.sync.aligned.m8n8.x4.shared.b16 {%0,%1,%2,%3}, [%4];\n"
                 : "=r"(r[0]), "=r"(r[1]), "=r"(r[2]), "=r"(r[3]) : "r"(addr));
}
__device__ __forceinline__ void ldm4t(uint32_t* r, uint32_t addr) {
    asm volatile("ldmatrix.sync.aligned.m8n8.x4.trans.shared.b16 {%0,%1,%2,%3}, [%4];\n"
                 : "=r"(r[0]), "=r"(r[1]), "=r"(r[2]), "=r"(r[3]) : "r"(addr));
}
__device__ __forceinline__ void mma_f16(float* c, const uint32_t* a, const uint32_t* b) {
    asm volatile(
        "mma.sync.aligned.m16n8k16.row.col.f32.f16.f16.f32 "
        "{%0,%1,%2,%3}, {%4,%5,%6,%7}, {%8,%9}, {%0,%1,%2,%3};\n"
        : "+f"(c[0]), "+f"(c[1]), "+f"(c[2]), "+f"(c[3])
        : "r"(a[0]), "r"(a[1]), "r"(a[2]), "r"(a[3]), "r"(b[0]), "r"(b[1]));
}

// ---------------- weight -> fragment converter (fp16 hi/lo) -----------------
__global__ void wfrag(const float* __restrict__ W, uint32_t* __restrict__ out,
                      int Ndim, int Kdim, int NT8)
{
    const int KT16 = Kdim >> 4;
    size_t idx = (size_t)blockIdx.x * 256 + threadIdx.x;
    size_t total = (size_t)NT8 * KT16 * 128;
    if (idx >= total) return;
    int r     = (int)(idx & 1);
    int l     = (int)((idx >> 1) & 31);
    int plane = (int)((idx >> 6) & 1);
    size_t ft = idx >> 7;
    int k16 = (int)(ft % KT16);
    int n8  = (int)(ft / KT16);
    int n = n8 * 8 + (l >> 2);
    int k = k16 * 16 + (l & 3) * 2 + r * 8;
    float v0 = 0.f, v1 = 0.f;
    if (n < Ndim) {
        float2 vv = *(const float2*)&W[(size_t)n * Kdim + k];
        v0 = vv.x; v1 = vv.y;
    }
    __half h0 = __float2half_rn(v0), h1 = __float2half_rn(v1);
    uint32_t val = (plane == 0)
        ? pk2h(h0, h1)
        : pk2h(__float2half_rn(v0 - __half2float(h0)),
               __float2half_rn(v1 - __half2float(h1)));
    out[idx] = val;
}

__global__ void biascat(const float* __restrict__ bq, const float* __restrict__ bk,
                        const float* __restrict__ bv, float* __restrict__ out)
{
    int i = blockIdx.x * 256 + threadIdx.x;
    if (i < LNUM * 512) {
        int l = i >> 9, c = i & 511;
        out[l*1536 + c]        = bq[i];
        out[l*1536 + 512 + c]  = bk[i];
        out[l*1536 + 1024 + c] = bv[i];
    }
}

#define ASTR 40

// ======================================================================
// gemm_h: A fp16 (pre-converted), B fp16 hi plane only. 1 MMA/k-step.
// modes: 0 C fp32 (+extra resid), 2 gate -> Ch fp16, 3 qkv split (q,k fp32; v fp16)
// Ndim multiple of 128 (no column guards).
// ======================================================================
__global__ __launch_bounds__(256, 2)
void gemm_h(const __half* __restrict__ A, const uint32_t* __restrict__ Bf,
            float* __restrict__ C, __half* __restrict__ Ch,
            const float* __restrict__ bias, const float* __restrict__ extra,
            int Mdim, int Ndim, int Kdim, int mode)
{
    __shared__ __align__(16) __half Asm[128][ASTR];

    const int tid  = threadIdx.x;
    const int lane = tid & 31;
    const int warp = tid >> 5;
    const int wm = (warp & 1) * 64;
    const int wn = (warp >> 1) * 32;
    const int bm = blockIdx.y * 128;
    const int bn = blockIdx.x * 128;
    const int KT16 = Kdim >> 4;
    const int n8_0 = (bn + wn) >> 3;

    float acc[4][4][4];
    #pragma unroll
    for (int i = 0; i < 4; i++)
        #pragma unroll
        for (int j = 0; j < 4; j++)
            #pragma unroll
            for (int t = 0; t < 4; t++) acc[i][j][t] = 0.f;

    const int a_m = lane & 15;
    const int a_k = (lane >> 4) << 3;
    const uint32_t sA = (uint32_t)__cvta_generic_to_shared(&Asm[0][0]);

    const int KT = Kdim >> 5;
    for (int kt = 0; kt < KT; kt++) {
        #pragma unroll
        for (int u = 0; u < 2; u++) {
            int f = tid + u * 256;
            int row = f >> 2;
            int c8 = (f & 3) * 8;
            *(uint4*)&Asm[row][c8] =
                *(const uint4*)&A[(size_t)(bm + row) * Kdim + kt*32 + c8];
        }
        __syncthreads();

        #pragma unroll
        for (int ks = 0; ks < 2; ks++) {
            uint32_t bhf[4][2];
            const uint32_t* fb = Bf + ((size_t)n8_0 * KT16 + (kt*2 + ks)) * 128 + lane * 2;
            #pragma unroll
            for (int nt = 0; nt < 4; nt++) {
                uint2 hv = *(const uint2*)(fb + (size_t)nt * KT16 * 128);
                bhf[nt][0] = hv.x; bhf[nt][1] = hv.y;
            }
            #pragma unroll
            for (int mt = 0; mt < 4; mt++) {
                uint32_t ah[4];
                uint32_t addr = sA + (uint32_t)(((wm + mt*16 + a_m) * ASTR) + ks*16 + a_k) * 2;
                ldm4(ah, addr);
                #pragma unroll
                for (int nt = 0; nt < 4; nt++)
                    mma_f16(acc[mt][nt], ah, bhf[nt]);
            }
        }
        __syncthreads();
    }

    const int gr = lane >> 2;
    const int gc = (lane & 3) * 2;
    #pragma unroll
    for (int mt = 0; mt < 4; mt++) {
        #pragma unroll
        for (int nt = 0; nt < 4; nt++) {
            const float* cp = acc[mt][nt];
            int row = bm + wm + mt*16 + gr;
            int col = bn + wn + nt*8 + gc;
            #pragma unroll
            for (int half = 0; half < 2; half++) {
                int rr = row + half*8;
                float v0 = cp[half*2 + 0];
                float v1 = cp[half*2 + 1];
                if (bias) { v0 += bias[col]; v1 += bias[col + 1]; }
                if (mode == 0) {
                    if (extra) {
                        v0 += extra[(size_t)rr * Ndim + col];
                        v1 += extra[(size_t)rr * Ndim + col + 1];
                    }
                    float2 st = make_float2(v0, v1);
                    *(float2*)&C[(size_t)rr * Ndim + col] = st;
                } else if (mode == 2) {
                    float a0 = extra[(size_t)rr * Ndim + col];
                    float a1 = extra[(size_t)rr * Ndim + col + 1];
                    __half2 hh = __floats2half2_rn(a0 / (1.f + expf(-v0)),
                                                   a1 / (1.f + expf(-v1)));
                    *(__half2*)&Ch[(size_t)rr * Ndim + col] = hh;
                } else { // mode 3
                    if (col < 1024) {
                        float2 st = make_float2(v0, v1);
                        *(float2*)&C[(size_t)(col >> 9) * ((size_t)ROWS * ID_)
                                     + (size_t)rr * ID_ + (col & 511)] = st;
                    } else {
                        __half2 hh = __floats2half2_rn(v0, v1);
                        *(__half2*)&Ch[(size_t)rr * ID_ + (col & 511)] = hh;
                    }
                }
            }
        }
    }
}

// ======================================================================
// gemm_f3 (proj only): A fp32 split hi/lo (3 MMAs), B hi/lo. Out fp32 [rh][MMP].
// ======================================================================
#define PLANE_ELEMS (128*ASTR)
#define PLANE_BYTES (PLANE_ELEMS*2)
__global__ __launch_bounds__(256, 2)
void gemm_f3(const float* __restrict__ A, const uint32_t* __restrict__ Bf,
             float* __restrict__ C, int Mdim, int Ndim, int Kdim, float alpha)
{
    __shared__ __align__(16) __half Asm[2][128][ASTR];

    const int tid  = threadIdx.x;
    const int lane = tid & 31;
    const int warp = tid >> 5;
    const int wm = (warp & 1) * 64;
    const int wn = (warp >> 1) * 32;
    const int bm = blockIdx.y * 128;
    const int bn = blockIdx.x * 128;
    const int KT16 = Kdim >> 4;
    const int n8_0 = (bn + wn) >> 3;

    const int r0 = tid >> 3;
    const int kk = (tid & 7) * 4;

    float acc[4][4][4];
    #pragma unroll
    for (int i = 0; i < 4; i++)
        #pragma unroll
        for (int j = 0; j < 4; j++)
            #pragma unroll
            for (int t = 0; t < 4; t++) acc[i][j][t] = 0.f;

    const int a_m = lane & 15;
    const int a_k = (lane >> 4) << 3;
    const uint32_t sA = (uint32_t)__cvta_generic_to_shared(&Asm[0][0][0]);

    const int KT = Kdim >> 5;
    for (int kt = 0; kt < KT; kt++) {
        #pragma unroll
        for (int u = 0; u < 4; u++) {
            const int row = r0 + u * 32;
            float4 v = *(const float4*)&A[(size_t)(bm + row) * Kdim + kt*32 + kk];
            uint2 hi, lo;
            splitf4h(v, hi, lo);
            *(uint2*)&Asm[0][row][kk] = hi;
            *(uint2*)&Asm[1][row][kk] = lo;
        }
        __syncthreads();

        #pragma unroll
        for (int ks = 0; ks < 2; ks++) {
            uint32_t bhf[4][2], blf[4][2];
            const uint32_t* fb = Bf + ((size_t)n8_0 * KT16 + (kt*2 + ks)) * 128 + lane * 2;
            #pragma unroll
            for (int nt = 0; nt < 4; nt++) {
                const uint32_t* fp2 = fb + (size_t)nt * KT16 * 128;
                uint2 h  = *(const uint2*)fp2;
                uint2 lo = *(const uint2*)(fp2 + 64);
                bhf[nt][0] = h.x;  bhf[nt][1] = h.y;
                blf[nt][0] = lo.x; blf[nt][1] = lo.y;
            }
            #pragma unroll
            for (int mt = 0; mt < 4; mt++) {
                uint32_t ah[4], al[4];
                uint32_t addr = sA + (uint32_t)(((wm + mt*16 + a_m) * ASTR) + ks*16 + a_k) * 2;
                ldm4(ah, addr);
                ldm4(al, addr + PLANE_BYTES);
                #pragma unroll
                for (int nt = 0; nt < 4; nt++) {
                    mma_f16(acc[mt][nt], ah, bhf[nt]);
                    mma_f16(acc[mt][nt], ah, blf[nt]);
                    mma_f16(acc[mt][nt], al, bhf[nt]);
                }
            }
        }
        __syncthreads();
    }

    const int gr = lane >> 2;
    const int gc = (lane & 3) * 2;
    #pragma unroll
    for (int mt = 0; mt < 4; mt++) {
        #pragma unroll
        for (int nt = 0; nt < 4; nt++) {
            const float* cp = acc[mt][nt];
            int row = bm + wm + mt*16 + gr;
            int col = bn + wn + nt*8 + gc;
            #pragma unroll
            for (int half = 0; half < 2; half++) {
                int rr = row + half*8;
                #pragma unroll
                for (int j = 0; j < 2; j++) {
                    int cc = col + j;
                    if (cc < Ndim)
                        C[(size_t)rr * MMP + cc] = cp[half*2 + j] * alpha;
                }
            }
        }
    }
}

// ======================================================================
// ctx_mma: single-fp16 kp^T @ v over 256-seq chunk -> fp32 partials
// ======================================================================
#define KPITCH 280
#define VPITCH 72
__global__ __launch_bounds__(256, 1)
void ctx_mma(const __half* __restrict__ kp, const __half* __restrict__ v,
             float* __restrict__ part)
{
    __shared__ __align__(16) __half Kp[32][KPITCH];
    __shared__ __align__(16) __half Vs[32][VPITCH];

    const int tid = threadIdx.x;
    const int lane = tid & 31;
    const int warp = tid >> 5;
    const int kc = blockIdx.x;
    const int bh = blockIdx.y;
    const int b = bh >> 3, h = bh & 7;

    const int nmt = (warp == 0) ? 3 : 2;
    int mts[3];
    mts[0] = 2*warp; mts[1] = 2*warp + 1; mts[2] = 16;

    float acc[3][8][4];
    #pragma unroll
    for (int t = 0; t < 3; t++)
        #pragma unroll
        for (int n = 0; n < 8; n++)
            #pragma unroll
            for (int j = 0; j < 4; j++) acc[t][n][j] = 0.f;

    const __half* kpb = kp + ((size_t)(b * SEQ) * H_ + h) * MMP;
    const __half* vb  = v  + ((size_t)(b * SEQ) * H_ + h) * DH_;

    const uint32_t sK = (uint32_t)__cvta_generic_to_shared(&Kp[0][0]);
    const uint32_t sV = (uint32_t)__cvta_generic_to_shared(&Vs[0][0]);
    const int r7 = lane & 7;

    for (int it = 0; it < 8; it++) {
        const int n0 = kc * 256 + it * 32;
        // Kp fill: 32 rows x 272 halfs = 34 uint4/row
        for (int f = tid; f < 32*34; f += 256) {
            int nn = f / 34, c8 = (f % 34) * 8;
            *(uint4*)&Kp[nn][c8] =
                *(const uint4*)&kpb[(size_t)(n0 + nn) * (H_*MMP) + c8];
        }
        // Vs fill: 32 rows x 64 halfs = 8 uint4/row -> exactly 256
        {
            int nn = tid >> 3, c8 = (tid & 7) * 8;
            *(uint4*)&Vs[nn][c8] =
                *(const uint4*)&vb[(size_t)(n0 + nn) * (H_*DH_) + c8];
        }
        __syncthreads();

        #pragma unroll
        for (int ks = 0; ks < 2; ks++) {
            uint32_t bhf[8][2];
            #pragma unroll
            for (int g = 0; g < 4; g++) {
                int row = ks*16 + ((lane >> 3) & 1) * 8 + r7;
                int col = g*16 + (lane >> 4) * 8;
                uint32_t r[4];
                ldm4t(r, sV + (uint32_t)(row * VPITCH + col) * 2);
                bhf[2*g][0] = r[0]; bhf[2*g][1] = r[1];
                bhf[2*g+1][0] = r[2]; bhf[2*g+1][1] = r[3];
            }
            #pragma unroll
            for (int t = 0; t < 3; t++) {
                if (t < nmt) {
                    int m0 = mts[t] * 16;
                    int row = ks*16 + ((lane >> 4) & 1) * 8 + r7;
                    int col = m0 + ((lane >> 3) & 1) * 8;
                    uint32_t ah[4];
                    ldm4t(ah, sK + (uint32_t)(row * KPITCH + col) * 2);
                    #pragma unroll
                    for (int nt = 0; nt < 8; nt++)
                        mma_f16(acc[t][nt], ah, bhf[nt]);
                }
            }
        }
        __syncthreads();
    }

    const int gr = lane >> 2;
    const int gc = (lane & 3) * 2;
    float* pb = part + ((size_t)(bh * 8 + kc)) * 272 * 64;
    #pragma unroll
    for (int t = 0; t < 3; t++) {
        if (t < nmt) {
            int m0 = mts[t] * 16;
            #pragma unroll
            for (int nt = 0; nt < 8; nt++) {
                int e = nt*8 + gc;
                pb[(size_t)(m0 + gr) * 64 + e]     = acc[t][nt][0];
                pb[(size_t)(m0 + gr) * 64 + e + 1] = acc[t][nt][1];
                pb[(size_t)(m0 + gr + 8) * 64 + e]     = acc[t][nt][2];
                pb[(size_t)(m0 + gr + 8) * 64 + e + 1] = acc[t][nt][3];
            }
        }
    }
}

// ---------------- reduceT: sum partials -> ctxT fp16 [bh][e][m] (+ks row) ---
__global__ void reduceT(const float* __restrict__ part, const float* __restrict__ ks,
                        __half* __restrict__ ctxT)
{
    const int bh = blockIdx.y;
    const int m0 = blockIdx.x * 64;
    const int mw = (272 - m0 < 64) ? (272 - m0) : 64;
    __shared__ float sm[64][65];
    const int t = threadIdx.x;
    const int e  = t & 63;
    const int mr = t >> 6;
    for (int mm = mr; mm < mw; mm += 4) {
        float s = 0.f;
        #pragma unroll
        for (int kc = 0; kc < 8; kc++)
            s += part[(((size_t)(bh*8 + kc)) * 272 + m0 + mm) * 64 + e];
        sm[mm][e] = s;
    }
    __syncthreads();
    const int m  = t & 63;
    const int er = t >> 6;
    for (int ee = er; ee < 80; ee += 4) {
        if (m0 + m < 288) {
            float val = 0.f;
            if (m < mw) {
                if (ee < 64)       val = sm[m][ee];
                else if (ee == 64) val = ks[(size_t)bh * MMP + m0 + m];
            }
            ctxT[((size_t)bh * 80 + ee) * 288 + m0 + m] = __float2half(val);
        }
    }
}

// ======================================================================
// attn_mma: qp(fp16) @ ctxT^T(fp16); col 64 = dsum; out fp16 att
// ======================================================================
#define APITCH 24
__global__ __launch_bounds__(256, 2)
void attn_mma(const __half* __restrict__ qp, const __half* __restrict__ ctxT,
              __half* __restrict__ out)
{
    __shared__ __align__(16) __half As[128][APITCH];
    __shared__ __align__(16) __half Bs[80][APITCH];

    const int tid = threadIdx.x;
    const int lane = tid & 31;
    const int warp = tid >> 5;
    const int bm = blockIdx.x * 128;
    const int bh = blockIdx.y;
    const int b = bh >> 3, h = bh & 7;
    const int wm = warp * 16;

    const __half* qpb = qp + ((size_t)(b * SEQ) * H_ + h) * MMP;
    const __half* cb  = ctxT + (size_t)bh * 80 * 288;

    float acc[9][4];
    #pragma unroll
    for (int n = 0; n < 9; n++)
        #pragma unroll
        for (int j = 0; j < 4; j++) acc[n][j] = 0.f;

    const uint32_t sA = (uint32_t)__cvta_generic_to_shared(&As[0][0]);
    const uint32_t sB = (uint32_t)__cvta_generic_to_shared(&Bs[0][0]);
    const int a_m = lane & 15;
    const int a_k = (lane >> 4) << 3;
    const int b_n = (lane & 7) | ((lane & 16) >> 1);
    const int b_k = lane & 8;

    for (int k16 = 0; k16 < 17; k16++) {
        const int k0 = k16 * 16;
        // A: 128 rows x 16 halfs = 2 uint4/row = 256 loads
        {
            int row = tid >> 1, c8 = (tid & 1) * 8;
            *(uint4*)&As[row][c8] =
                *(const uint4*)&qpb[(size_t)(bm + row) * (H_*MMP) + k0 + c8];
        }
        // B: 80 rows x 16 halfs = 160 loads
        if (tid < 160) {
            int row = tid >> 1, c8 = (tid & 1) * 8;
            *(uint4*)&Bs[row][c8] =
                *(const uint4*)&cb[(size_t)row * 288 + k0 + c8];
        }
        __syncthreads();

        uint32_t bhf[10][2];
        #pragma unroll
        for (int p = 0; p < 5; p++) {
            uint32_t r[4];
            ldm4(r, sB + (uint32_t)((p*16 + b_n) * APITCH + b_k) * 2);
            bhf[2*p][0] = r[0]; bhf[2*p][1] = r[1];
            bhf[2*p+1][0] = r[2]; bhf[2*p+1][1] = r[3];
        }
        {
            uint32_t ah[4];
            ldm4(ah, sA + (uint32_t)((wm + a_m) * APITCH + a_k) * 2);
            #pragma unroll
            for (int nt = 0; nt < 9; nt++)
                mma_f16(acc[nt], ah, bhf[nt]);
        }
        __syncthreads();
    }

    const int gr = lane >> 2;
    const int gc = (lane & 3) * 2;
    float d0 = __shfl_sync(0xffffffffu, acc[8][0], gr * 4);
    float d1 = __shfl_sync(0xffffffffu, acc[8][2], gr * 4);
    const float dinv0 = 1.f / (d0 + 1e-8f);
    const float dinv1 = 1.f / (d1 + 1e-8f);

    const size_t row0 = ((size_t)(b * SEQ + bm + wm + gr) * H_ + h) * DH_;
    const size_t row1 = row0 + (size_t)8 * H_ * DH_;
    #pragma unroll
    for (int nt = 0; nt < 8; nt++) {
        int e = nt*8 + gc;
        *(__half2*)&out[row0 + e] = __floats2half2_rn(acc[nt][0]*dinv0, acc[nt][1]*dinv0);
        *(__half2*)&out[row1 + e] = __floats2half2_rn(acc[nt][2]*dinv1, acc[nt][3]*dinv1);
    }
}

// ---------------- LayerNorm (fp16 out) -----------------
__global__ void ln_kernel(const float* __restrict__ x, const float* __restrict__ g,
                          const float* __restrict__ b, __half* __restrict__ out)
{
    const int r = blockIdx.x;
    const int t = threadIdx.x;
    const float4 v = ((const float4*)(x + (size_t)r * D_))[t];
    float s  = v.x + v.y + v.z + v.w;
    float ss = v.x*v.x + v.y*v.y + v.z*v.z + v.w*v.w;
    __shared__ float rs[128], rss[128];
    rs[t] = s; rss[t] = ss;
    __syncthreads();
    for (int o = 64; o > 0; o >>= 1) {
        if (t < o) { rs[t] += rs[t+o]; rss[t] += rss[t+o]; }
        __syncthreads();
    }
    const float mu   = rs[0] * (1.f / D_);
    const float var  = rss[0] * (1.f / D_) - mu * mu;
    const float rstd = rsqrtf(var + 1e-5f);
    const float4 gg = ((const float4*)g)[t];
    const float4 bb = ((const float4*)b)[t];
    __half2 p0 = __floats2half2_rn((v.x - mu) * rstd * gg.x + bb.x,
                                   (v.y - mu) * rstd * gg.y + bb.y);
    __half2 p1 = __floats2half2_rn((v.z - mu) * rstd * gg.z + bb.z,
                                   (v.w - mu) * rstd * gg.w + bb.w);
    uint2 st;
    st.x = *reinterpret_cast<uint32_t*>(&p0);
    st.y = *reinterpret_cast<uint32_t*>(&p1);
    *(uint2*)&out[(size_t)r * D_ + t * 4] = st;
}

// ---------------- FAVOR postprocess: fp32 in, fp16 out ----
__global__ __launch_bounds__(256)
void favor_post3(const float* __restrict__ fp, __half* __restrict__ fph,
                 const float* __restrict__ data, float ratio)
{
    const int lane = threadIdx.x & 31;
    const int w    = threadIdx.x >> 5;
    const size_t rh = (size_t)blockIdx.x * 8 + w;
    const int isQ = rh < (size_t)RH;

    const float* prow = fp + rh * MMP;
    __half* orow = fph + rh * MMP;
    const float* drow = data + rh * DH_;

    float2 d2 = ((const float2*)drow)[lane];
    float s = d2.x*d2.x + d2.y*d2.y;
    #pragma unroll
    for (int o = 16; o > 0; o >>= 1) s += __shfl_xor_sync(0xffffffffu, s, o);
    const float diag = s * 0.0625f;

    float v[9];
    #pragma unroll
    for (int j = 0; j < 9; j++) {
        int m = j*32 + lane;
        v[j] = (m < MM) ? prow[m] : -1e30f;
    }

    if (isQ) {
        float mx = v[0];
        #pragma unroll
        for (int j = 1; j < 9; j++) mx = fmaxf(mx, v[j]);
        #pragma unroll
        for (int o = 16; o > 0; o >>= 1) mx = fmaxf(mx, __shfl_xor_sync(0xffffffffu, mx, o));
        #pragma unroll
        for (int j = 0; j < 9; j++) {
            int m = j*32 + lane;
            if (m < MM)       orow[m] = __float2half(ratio * (expf(v[j] - diag - mx) + 1e-4f));
            else if (m < MMP) orow[m] = __float2half(0.f);
        }
    } else {
        #pragma unroll
        for (int j = 0; j < 9; j++) {
            int m = j*32 + lane;
            if (m < MM)       orow[m] = __float2half(ratio * expf(v[j] - diag + 1e-4f));
            else if (m < MMP) orow[m] = __float2half(0.f);
        }
    }
}

// ---------------- ksum two-stage (fp16 in) ---------------
__global__ void ksum1(const __half* __restrict__ kp, float* __restrict__ part)
{
    const int bh = blockIdx.y;
    const int chunk = blockIdx.x;
    const int m = threadIdx.x;
    if (m >= MMP) return;
    const int b = bh >> 3, h = bh & 7;
    const __half* base = kp + ((size_t)(b * SEQ + chunk * 256) * H_ + h) * MMP + m;
    const size_t stride = (size_t)H_ * MMP;
    float s0 = 0.f, s1 = 0.f, s2 = 0.f, s3 = 0.f;
    for (int n = 0; n < 256; n += 4) {
        s0 += __half2float(base[(n+0) * stride]);
        s1 += __half2float(base[(n+1) * stride]);
        s2 += __half2float(base[(n+2) * stride]);
        s3 += __half2float(base[(n+3) * stride]);
    }
    part[((size_t)bh * 8 + chunk) * MMP + m] = (s0 + s1) + (s2 + s3);
}
__global__ void ksum2(const float* __restrict__ part, float* __restrict__ ks)
{
    const int bh = blockIdx.x;
    const int m = threadIdx.x;
    if (m >= MMP) return;
    float s = 0.f;
    #pragma unroll
    for (int c = 0; c < 8; c++) s += part[((size_t)bh * 8 + c) * MMP + m];
    ks[(size_t)bh * MMP + m] = s;
}

// ---------------- depthwise conv + SiLU (fp16 in/out) ---------------
#define DC_CH 128
#define DC_TN 32
__global__ __launch_bounds__(256)
void dwconv2(const __half* __restrict__ gin, const float* __restrict__ w,
             const float* __restrict__ bias, __half* __restrict__ out)
{
    __shared__ float sin_[DC_TN + 30][DC_CH];
    __shared__ float sw[DC_CH * KW];

    const int c0 = blockIdx.x * DC_CH;
    const int n0 = blockIdx.y * DC_TN;
    const int b  = blockIdx.z;
    const int t  = threadIdx.x;

    for (int i = t; i < DC_CH * KW; i += 256)
        sw[i] = w[(size_t)c0 * KW + i];
    #pragma unroll
    for (int u = 0; u < (DC_TN + 30) * DC_CH / 256; u++) {
        int f = t + u * 256;
        int rowi = f >> 7;
        int ch = f & 127;
        int n = n0 + rowi - 15;
        sin_[rowi][ch] = ((unsigned)n < SEQ)
            ? __half2float(gin[((size_t)(b * SEQ + n) << 10) + c0 + ch]) : 0.f;
    }
    __syncthreads();

    const int ch = t & 127;
    const int nl0 = (t >> 7) * 16;

    float wr[KW];
    #pragma unroll
    for (int k = 0; k < KW; k++) wr[k] = sw[ch * KW + k];
    const float bb = bias[c0 + ch];

    #pragma unroll
    for (int i = 0; i < 16; i++) {
        float acc = bb;
        #pragma unroll
        for (int k = 0; k < KW; k++)
            acc += sin_[nl0 + i + k][ch] * wr[k];
        float o = acc / (1.f + expf(-acc));
        out[((size_t)(b * SEQ + n0 + nl0 + i) << 10) + c0 + ch] = __float2half(o);
    }
}

// ---------------- host orchestration ----------------------------------------
static inline void run_gemm_h(const __half* A, const uint32_t* Bf, float* C,
                              __half* Ch, const float* bias, const float* extra,
                              int Mdim, int Ndim, int Kdim, int mode)
{
    dim3 grid(Ndim / 128, Mdim / 128);
    gemm_h<<<grid, 256>>>(A, Bf, C, Ch, bias, extra, Mdim, Ndim, Kdim, mode);
}
static inline void run_wfrag(const float* W, uint32_t* out, int Ndim, int Kdim, int NT8)
{
    size_t total = (size_t)NT8 * (Kdim >> 4) * 128;
    wfrag<<<(unsigned)((total + 255) / 256), 256>>>(W, out, Ndim, Kdim, NT8);
}

extern "C" void kernel_launch(void* const* d_in, const int* in_sizes, int n_in,
                              void* d_out, int out_size)
{
    const float* x    = (const float*)d_in[0];
    const float* ln1g = (const float*)d_in[1];
    const float* ln1b = (const float*)d_in[2];
    const float* wq   = (const float*)d_in[3];
    const float* bq   = (const float*)d_in[4];
    const float* wk   = (const float*)d_in[5];
    const float* bk   = (const float*)d_in[6];
    const float* wv   = (const float*)d_in[7];
    const float* bv   = (const float*)d_in[8];
    const float* wo   = (const float*)d_in[9];
    const float* bo   = (const float*)d_in[10];
    const float* proj = (const float*)d_in[11];
    const float* ln2g = (const float*)d_in[12];
    const float* ln2b = (const float*)d_in[13];
    const float* pw1w = (const float*)d_in[14];
    const float* pw1b = (const float*)d_in[15];
    const float* dww  = (const float*)d_in[16];
    const float* dwb  = (const float*)d_in[17];
    const float* pw2w = (const float*)d_in[18];
    const float* pw2b = (const float*)d_in[19];
    float* xo = (float*)d_out;

    __half *h, *vh, *fph, *ctxT, *att, *glu, *dw;
    float *qk, *fp, *ks, *part, *cpart, *ya, *qkvb;
    uint32_t* wf;
    cudaGetSymbolAddress((void**)&h,     g_h);
    cudaGetSymbolAddress((void**)&qk,    g_qk);
    cudaGetSymbolAddress((void**)&vh,    g_vh);
    cudaGetSymbolAddress((void**)&fp,    g_fp);
    cudaGetSymbolAddress((void**)&fph,   g_fph);
    cudaGetSymbolAddress((void**)&ks,    g_ks);
    cudaGetSymbolAddress((void**)&part,  g_part);
    cudaGetSymbolAddress((void**)&cpart, g_cpart);
    cudaGetSymbolAddress((void**)&ctxT,  g_ctxT);
    cudaGetSymbolAddress((void**)&att,   g_att);
    cudaGetSymbolAddress((void**)&ya,    g_ya);
    cudaGetSymbolAddress((void**)&glu,   g_glu);
    cudaGetSymbolAddress((void**)&dw,    g_dw);
    cudaGetSymbolAddress((void**)&qkvb,  g_qkvbias);
    cudaGetSymbolAddress((void**)&wf,    g_wfrag);

    __half* qph = fph;
    __half* kph = fph + (size_t)RH * MMP;

    const size_t OFF_WQ = 0;
    const size_t OFF_WO = OFF_WQ + 3*FR_QKV;
    const size_t OFF_P1 = OFF_WO + FR_QKV;
    const size_t OFF_P2 = OFF_P1 + FR_PW1;
    const size_t OFF_PR = OFF_P2 + FR_PW2;

    for (int l = 0; l < LNUM; l++) {
        uint32_t* lw = wf + (size_t)l * FR_LSTR;
        run_wfrag(wq   + (size_t)l*ID_*D_,    lw + OFF_WQ,            512, 512, 64);
        run_wfrag(wk   + (size_t)l*ID_*D_,    lw + OFF_WQ + FR_QKV,   512, 512, 64);
        run_wfrag(wv   + (size_t)l*ID_*D_,    lw + OFF_WQ + 2*FR_QKV, 512, 512, 64);
        run_wfrag(wo   + (size_t)l*ID_*D_,    lw + OFF_WO, 512, 512, 64);
        run_wfrag(pw1w + (size_t)l*2048*D_,   lw + OFF_P1, 2048, 512, 256);
        run_wfrag(pw2w + (size_t)l*D_*INNER_, lw + OFF_P2, 512, 1024, 64);
        run_wfrag(proj + (size_t)l*MM*DH_,    lw + OFF_PR, 266, 64, 48);
    }
    biascat<<<(LNUM*512 + 255)/256, 256>>>(bq, bk, bv, qkvb);

    cudaMemcpyAsync(xo, x, (size_t)ROWS * D_ * sizeof(float),
                    cudaMemcpyDeviceToDevice);

    const float dn    = (float)(1.0 / sqrt(sqrt(64.0)));
    const float ratio = (float)(1.0 / sqrt(266.0));

    for (int l = 0; l < LNUM; l++) {
        uint32_t* lw = wf + (size_t)l * FR_LSTR;

        ln_kernel<<<ROWS, 128>>>(xo, ln1g + (size_t)l*D_, ln1b + (size_t)l*D_, h);
        // fused QKV: q,k fp32 into qk; v fp16 into vh
        run_gemm_h(h, lw + OFF_WQ, qk, vh, qkvb + (size_t)l*1536, nullptr,
                   ROWS, 1536, D_, 3);
        // proj (feeds exp): fp32 A split, 3-term
        {
            dim3 grid((MM + 127) / 128, (2*RH) / 128);
            gemm_f3<<<grid, 256>>>(qk, lw + OFF_PR, fp, 2*RH, MM, DH_, dn);
        }
        favor_post3<<<2*RH/8, 256>>>(fp, fph, qk, ratio);
        {
            dim3 k1(8, NBH);
            ksum1<<<k1, 288>>>(kph, part);
            ksum2<<<NBH, 288>>>(part, ks);
            dim3 cg(8, NBH);
            ctx_mma<<<cg, 256>>>(kph, vh, cpart);
            dim3 rg(5, NBH);
            reduceT<<<rg, 256>>>(cpart, ks, ctxT);
            dim3 ag(SEQ / 128, NBH);
            attn_mma<<<ag, 256>>>(qph, ctxT, att);
        }
        run_gemm_h(att, lw + OFF_WO, xo, nullptr, bo + (size_t)l*D_, xo,
                   ROWS, D_, ID_, 0);
        ln_kernel<<<ROWS, 128>>>(xo, ln2g + (size_t)l*D_, ln2b + (size_t)l*D_, h);
        run_gemm_h(h, lw + OFF_P1, ya, nullptr, pw1b + (size_t)l*2048, nullptr,
                   ROWS, INNER_, D_, 0);
        run_gemm_h(h, lw + OFF_P1 + (size_t)128*32*128, nullptr, glu,
                   pw1b + (size_t)l*2048 + INNER_, ya, ROWS, INNER_, D_, 2);
        {
            dim3 dg(INNER_/DC_CH, SEQ/DC_TN, B_);
            dwconv2<<<dg, 256>>>(glu, dww + (size_t)l*INNER_*KW, dwb + (size_t)l*INNER_, dw);
        }
        run_gemm_h(dw, lw + OFF_P2, xo, nullptr, pw2b + (size_t)l*D_, xo,
                   ROWS, D_, INNER_, 0);
    }
}